// round 1
// baseline (speedup 1.0000x reference)
#include <cuda_runtime.h>

#define NB 4
#define NT 2048
#define NC 1024
#define NH 16
#define ND 64
#define NM (NB*NT)      // 8192 rows
#define N_QKV (3*NC)    // 3072

// Scratch (device globals — no allocations allowed)
__device__ float g_Q[(size_t)NB*NH*NT*ND];
__device__ float g_K[(size_t)NB*NH*NT*ND];
__device__ float g_V[(size_t)NB*NH*NT*ND];
__device__ float g_AO[(size_t)NM*NC];

__device__ __forceinline__ float neg_inf() { return __int_as_float(0xff800000u); }

// ---------------------------------------------------------------------------
// GEMM: C[m][n] = sum_k A[m][k] * W[n][k] + bias[n]   (both operands K-major)
// MODE 0: A = x (param), scatter output into g_Q/g_K/g_V per [3,H,Dh] split
// MODE 1: A = g_AO, write Cout[m*NC + n]
// 128x128 tile, BK=8, 256 threads, 8x8 accum per thread.
// ---------------------------------------------------------------------------
template<int MODE>
__global__ __launch_bounds__(256) void gemm_nt_kernel(
    const float* __restrict__ Ain, const float* __restrict__ W,
    const float* __restrict__ bias, float* __restrict__ Cout, int K)
{
    __shared__ float As[8][128];
    __shared__ float Bs[8][128];
    const int tid = threadIdx.x;
    const int tx  = tid & 15;
    const int ty  = tid >> 4;
    const int m0  = blockIdx.y * 128;
    const int n0b = blockIdx.x * 128;

    const float* A = (MODE == 0) ? Ain : g_AO;

    const int lrow = tid >> 1;          // 0..127
    const int lc4  = (tid & 1) * 4;     // 0 or 4

    const float* Aptr = A + (size_t)(m0  + lrow) * K + lc4;
    const float* Wptr = W + (size_t)(n0b + lrow) * K + lc4;

    float acc[8][8];
    #pragma unroll
    for (int i = 0; i < 8; i++)
        #pragma unroll
        for (int j = 0; j < 8; j++) acc[i][j] = 0.f;

    for (int k0 = 0; k0 < K; k0 += 8) {
        float4 av = *(const float4*)(Aptr + k0);
        float4 bv = *(const float4*)(Wptr + k0);
        As[lc4+0][lrow] = av.x; As[lc4+1][lrow] = av.y;
        As[lc4+2][lrow] = av.z; As[lc4+3][lrow] = av.w;
        Bs[lc4+0][lrow] = bv.x; Bs[lc4+1][lrow] = bv.y;
        Bs[lc4+2][lrow] = bv.z; Bs[lc4+3][lrow] = bv.w;
        __syncthreads();
        #pragma unroll
        for (int kk = 0; kk < 8; kk++) {
            float ra[8], rb[8];
            *(float4*)&ra[0] = *(const float4*)&As[kk][ty*8];
            *(float4*)&ra[4] = *(const float4*)&As[kk][ty*8+4];
            *(float4*)&rb[0] = *(const float4*)&Bs[kk][tx*8];
            *(float4*)&rb[4] = *(const float4*)&Bs[kk][tx*8+4];
            #pragma unroll
            for (int i = 0; i < 8; i++)
                #pragma unroll
                for (int j = 0; j < 8; j++)
                    acc[i][j] = fmaf(ra[i], rb[j], acc[i][j]);
        }
        __syncthreads();
    }

    const int n = n0b + tx * 8;
    float bv[8];
    #pragma unroll
    for (int j = 0; j < 8; j++) bv[j] = bias[n + j];

    if (MODE == 0) {
        // n -> (sel, h, d): qkv reshaped [3, H, Dh]. 8 cols stay in one (sel,h).
        const int sel = n >> 10;
        const int rem = n & 1023;
        const int h   = rem >> 6;
        const int d0  = rem & 63;
        float* dst = (sel == 0) ? g_Q : (sel == 1) ? g_K : g_V;
        #pragma unroll
        for (int i = 0; i < 8; i++) {
            int m = m0 + ty * 8 + i;
            int b = m >> 11;            // / NT
            int t = m & (NT - 1);
            float* p = dst + (((size_t)(b * NH + h) * NT + t) * ND + d0);
            float4 v0 = make_float4(acc[i][0]+bv[0], acc[i][1]+bv[1],
                                    acc[i][2]+bv[2], acc[i][3]+bv[3]);
            float4 v1 = make_float4(acc[i][4]+bv[4], acc[i][5]+bv[5],
                                    acc[i][6]+bv[6], acc[i][7]+bv[7]);
            *(float4*)p       = v0;
            *(float4*)(p + 4) = v1;
        }
    } else {
        #pragma unroll
        for (int i = 0; i < 8; i++) {
            int m = m0 + ty * 8 + i;
            float* p = Cout + (size_t)m * NC + n;
            float4 v0 = make_float4(acc[i][0]+bv[0], acc[i][1]+bv[1],
                                    acc[i][2]+bv[2], acc[i][3]+bv[3]);
            float4 v1 = make_float4(acc[i][4]+bv[4], acc[i][5]+bv[5],
                                    acc[i][6]+bv[6], acc[i][7]+bv[7]);
            *(float4*)p       = v0;
            *(float4*)(p + 4) = v1;
        }
    }
}

// ---------------------------------------------------------------------------
// Causal flash attention. grid = (T/128 q-tiles, B*H). 128 threads.
// Each thread owns one query row: q[64] and o[64] in registers, online
// softmax per-row (no cross-thread reductions). K/V tiles (64x64) in SMEM,
// read as float4 broadcasts (conflict-free).
// Output scattered to g_AO[b][t][h*64+d]  ([B,T,C] for the out-proj GEMM).
// ---------------------------------------------------------------------------
__global__ __launch_bounds__(128) void attn_kernel()
{
    __shared__ float Ks[64][64];
    __shared__ float Vs[64][64];

    const int qt  = blockIdx.x;
    const int bh  = blockIdx.y;
    const int tid = threadIdx.x;
    const int r   = qt * 128 + tid;          // this thread's query row

    const float* Qp = g_Q + (size_t)bh * NT * ND;
    const float* Kp = g_K + (size_t)bh * NT * ND;
    const float* Vp = g_V + (size_t)bh * NT * ND;

    const float scale = 0.125f;              // 1/sqrt(64)

    float q[64];
    {
        const float4* qr = (const float4*)(Qp + (size_t)r * ND);
        #pragma unroll
        for (int k4 = 0; k4 < 16; k4++) {
            float4 v = qr[k4];
            q[k4*4+0] = v.x * scale; q[k4*4+1] = v.y * scale;
            q[k4*4+2] = v.z * scale; q[k4*4+3] = v.w * scale;
        }
    }

    float m_ = neg_inf();
    float l  = 0.f;
    float o[64];
    #pragma unroll
    for (int d = 0; d < 64; d++) o[d] = 0.f;

    const int kend = qt * 128 + 128;         // exclusive key limit (tile-rounded)

    for (int kt = 0; kt < kend; kt += 64) {
        __syncthreads();
        {   // cooperative load of K,V tile: 64x64 floats each = 1024 float4
            const float4* kg = (const float4*)(Kp + (size_t)kt * ND);
            const float4* vg = (const float4*)(Vp + (size_t)kt * ND);
            float4* ks = (float4*)&Ks[0][0];
            float4* vs = (float4*)&Vs[0][0];
            #pragma unroll
            for (int i = 0; i < 8; i++) {
                int idx = tid + 128 * i;
                ks[idx] = kg[idx];
                vs[idx] = vg[idx];
            }
        }
        __syncthreads();

        #pragma unroll
        for (int jt = 0; jt < 64; jt += 16) {
            float s[16];
            #pragma unroll
            for (int j = 0; j < 16; j++) {
                const float4* kr = (const float4*)&Ks[jt + j][0];
                float a = 0.f;
                #pragma unroll
                for (int k4 = 0; k4 < 16; k4++) {
                    float4 kv = kr[k4];
                    a = fmaf(q[k4*4+0], kv.x, a);
                    a = fmaf(q[k4*4+1], kv.y, a);
                    a = fmaf(q[k4*4+2], kv.z, a);
                    a = fmaf(q[k4*4+3], kv.w, a);
                }
                int jg = kt + jt + j;
                s[j] = (jg <= r) ? a : neg_inf();
            }
            float tmax = s[0];
            #pragma unroll
            for (int j = 1; j < 16; j++) tmax = fmaxf(tmax, s[j]);
            float mnew = fmaxf(m_, tmax);
            float sc = __expf(m_ - mnew);    // 0 when m_ = -inf, 1 when unchanged
            l *= sc;
            #pragma unroll
            for (int d = 0; d < 64; d++) o[d] *= sc;
            m_ = mnew;
            #pragma unroll
            for (int j = 0; j < 16; j++) {
                float p = __expf(s[j] - mnew);   // 0 for masked keys
                l += p;
                const float4* vr = (const float4*)&Vs[jt + j][0];
                #pragma unroll
                for (int d4 = 0; d4 < 16; d4++) {
                    float4 vv = vr[d4];
                    o[d4*4+0] = fmaf(p, vv.x, o[d4*4+0]);
                    o[d4*4+1] = fmaf(p, vv.y, o[d4*4+1]);
                    o[d4*4+2] = fmaf(p, vv.z, o[d4*4+2]);
                    o[d4*4+3] = fmaf(p, vv.w, o[d4*4+3]);
                }
            }
        }
    }

    const float inv = 1.0f / l;
    const int b = bh >> 4;
    const int h = bh & 15;
    float* p = g_AO + ((size_t)(b * NT + r)) * NC + h * ND;
    #pragma unroll
    for (int d4 = 0; d4 < 16; d4++) {
        float4 v = make_float4(o[d4*4+0]*inv, o[d4*4+1]*inv,
                               o[d4*4+2]*inv, o[d4*4+3]*inv);
        ((float4*)p)[d4] = v;
    }
}

// ---------------------------------------------------------------------------
extern "C" void kernel_launch(void* const* d_in, const int* in_sizes, int n_in,
                              void* d_out, int out_size)
{
    const float* x     = (const float*)d_in[0];   // [4,2048,1024]
    const float* Wqkv  = (const float*)d_in[1];   // [3072,1024]
    const float* bqkv  = (const float*)d_in[2];   // [3072]
    const float* Wout  = (const float*)d_in[3];   // [1024,1024]
    const float* bout  = (const float*)d_in[4];   // [1024]
    // d_in[5] = mask: causal, applied analytically
    float* out = (float*)d_out;                   // [4,2048,1024]

    // 1) QKV projection + scatter
    gemm_nt_kernel<0><<<dim3(N_QKV/128, NM/128), 256>>>(x, Wqkv, bqkv, nullptr, NC);
    // 2) causal flash attention
    attn_kernel<<<dim3(NT/128, NB*NH), 128>>>();
    // 3) output projection
    gemm_nt_kernel<1><<<dim3(NC/128, NM/128), 256>>>(nullptr, Wout, bout, out, NC);
}

// round 6
// speedup vs baseline: 1.3947x; 1.3947x over previous
#include <cuda_runtime.h>

#define NB 4
#define NT 2048
#define NC 1024
#define NH 16
#define ND 64
#define NM (NB*NT)      // 8192 rows
#define N_QKV (3*NC)    // 3072

// Scratch (device globals — no allocations allowed)
__device__ float g_Q[(size_t)NB*NH*NT*ND];
__device__ float g_K[(size_t)NB*NH*NT*ND];
__device__ float g_V[(size_t)NB*NH*NT*ND];
__device__ float g_AO[(size_t)NM*NC];

__device__ __forceinline__ float neg_inf() { return __int_as_float(0xff800000u); }

__device__ __forceinline__ unsigned smem_u32(const void* p) {
    unsigned a;
    asm("{ .reg .u64 t; cvta.to.shared.u64 t, %1; cvt.u32.u64 %0, t; }"
        : "=r"(a) : "l"(p));
    return a;
}
__device__ __forceinline__ void cp_async16(unsigned dst, const void* src) {
    asm volatile("cp.async.cg.shared.global [%0], [%1], 16;" :: "r"(dst), "l"(src));
}
#define CP_COMMIT()  asm volatile("cp.async.commit_group;" ::: "memory")
#define CP_WAIT(n)   asm volatile("cp.async.wait_group %0;" :: "n"(n) : "memory")

__device__ __forceinline__ unsigned f2tf32(float f) {
    unsigned u;
    asm("cvt.rna.tf32.f32 %0, %1;" : "=r"(u) : "f"(f));
    return u;
}
__device__ __forceinline__ void mma_tf32(float c[4], const unsigned a[4], const unsigned b[2]) {
    asm volatile(
        "mma.sync.aligned.m16n8k8.row.col.f32.tf32.tf32.f32 "
        "{%0,%1,%2,%3}, {%4,%5,%6,%7}, {%8,%9}, {%0,%1,%2,%3};"
        : "+f"(c[0]), "+f"(c[1]), "+f"(c[2]), "+f"(c[3])
        : "r"(a[0]), "r"(a[1]), "r"(a[2]), "r"(a[3]), "r"(b[0]), "r"(b[1]));
}

// ===========================================================================
// mma.sync tf32 GEMM: C[m][n] = sum_k A[m][k]*W[n][k] + bias[n], K = 1024
// CTA tile 128x128, BK=16, 256 threads (8 warps, 2x4), 3-stage cp.async.
// SMEM rows stride 20 floats -> conflict-free fragment gathers.
// MODE 0: A = x, scatter into g_Q/g_K/g_V.  MODE 1: A = g_AO, write Cout.
// ===========================================================================
#define BM 128
#define BN 128
#define BK 16
#define SROW 20                              // floats per smem row (16 + 4 pad)
#define STAGE_FLOATS (2*128*SROW)            // A + B per stage = 5120 floats
#define STAGE_BYTES  (STAGE_FLOATS*4)        // 20480 B
#define NSLAB (NC/BK)                        // 64
#define GEMM_SMEM (3*STAGE_BYTES)            // 61440 B

template<int MODE>
__device__ __forceinline__ void load_slab(const float* __restrict__ A,
                                          const float* __restrict__ W,
                                          int m0, int n0, int slab, int st,
                                          unsigned sb, int tid)
{
    const unsigned abase = sb + st * STAGE_BYTES;
    const unsigned bbase = abase + 128*SROW*4;
    const float* ag = A + (size_t)m0 * NC + slab * BK;
    const float* wg = W + (size_t)n0 * NC + slab * BK;
    #pragma unroll
    for (int i = 0; i < 2; i++) {            // A: 128 rows x 4 float4 = 512
        int idx = tid + 256 * i;
        int row = idx >> 2, c4 = idx & 3;
        cp_async16(abase + row * (SROW*4) + c4 * 16, ag + (size_t)row * NC + c4 * 4);
    }
    #pragma unroll
    for (int i = 0; i < 2; i++) {            // B (= W rows): same pattern
        int idx = tid + 256 * i;
        int row = idx >> 2, c4 = idx & 3;
        cp_async16(bbase + row * (SROW*4) + c4 * 16, wg + (size_t)row * NC + c4 * 4);
    }
    CP_COMMIT();
}

template<int MODE>
__global__ __launch_bounds__(256) void gemm_mma(
    const float* __restrict__ Ain, const float* __restrict__ W,
    const float* __restrict__ bias, float* __restrict__ Cout)
{
    extern __shared__ float smem[];
    const unsigned sb = smem_u32(smem);
    const int tid  = threadIdx.x;
    const int wid  = tid >> 5, lane = tid & 31;
    const int wm   = wid >> 2;               // 0..1  (64 rows each)
    const int wn   = wid & 3;                // 0..3  (32 cols each)
    const int m0   = blockIdx.y * BM;
    const int n0   = blockIdx.x * BN;
    const float* A = (MODE == 0) ? Ain : g_AO;

    const int lr = lane >> 2;                // 0..7
    const int lc = lane & 3;                 // 0..3

    float acc[4][4][4];
    #pragma unroll
    for (int mt = 0; mt < 4; mt++)
        #pragma unroll
        for (int nt = 0; nt < 4; nt++)
            #pragma unroll
            for (int i = 0; i < 4; i++) acc[mt][nt][i] = 0.f;

    load_slab<MODE>(A, W, m0, n0, 0, 0, sb, tid);
    load_slab<MODE>(A, W, m0, n0, 1, 1, sb, tid);
    load_slab<MODE>(A, W, m0, n0, 2, 2, sb, tid);

    for (int i = 0; i < NSLAB; i++) {
        const int st = i % 3;
        const int rem = NSLAB - 1 - i;
        if (rem >= 2)      CP_WAIT(2);
        else if (rem == 1) CP_WAIT(1);
        else               CP_WAIT(0);
        __syncthreads();

        const float* As = smem + st * STAGE_FLOATS;
        const float* Bs = As + 128*SROW;

        #pragma unroll
        for (int ks = 0; ks < 2; ks++) {
            unsigned a[4][4], b[4][2];
            #pragma unroll
            for (int mt = 0; mt < 4; mt++) {
                const float* p = As + (wm*64 + mt*16 + lr) * SROW + ks*8 + lc;
                a[mt][0] = f2tf32(p[0]);
                a[mt][1] = f2tf32(p[8*SROW]);
                a[mt][2] = f2tf32(p[4]);
                a[mt][3] = f2tf32(p[8*SROW + 4]);
            }
            #pragma unroll
            for (int nt = 0; nt < 4; nt++) {
                const float* p = Bs + (wn*32 + nt*8 + lr) * SROW + ks*8 + lc;
                b[nt][0] = f2tf32(p[0]);
                b[nt][1] = f2tf32(p[4]);
            }
            #pragma unroll
            for (int mt = 0; mt < 4; mt++)
                #pragma unroll
                for (int nt = 0; nt < 4; nt++)
                    mma_tf32(acc[mt][nt], a[mt], b[nt]);
        }
        __syncthreads();

        if (i + 3 < NSLAB)
            load_slab<MODE>(A, W, m0, n0, i + 3, st, sb, tid);
    }

    // Epilogue: c0,c1 -> (row, col..col+1); c2,c3 -> (row+8, col..col+1)
    #pragma unroll
    for (int mt = 0; mt < 4; mt++) {
        const int row = m0 + wm*64 + mt*16 + lr;
        #pragma unroll
        for (int nt = 0; nt < 4; nt++) {
            const int col = n0 + wn*32 + nt*8 + 2*lc;
            const float b0 = bias[col], b1 = bias[col + 1];
            float2 v0 = make_float2(acc[mt][nt][0] + b0, acc[mt][nt][1] + b1);
            float2 v1 = make_float2(acc[mt][nt][2] + b0, acc[mt][nt][3] + b1);
            if (MODE == 0) {
                const int sel = col >> 10;
                const int h   = (col & 1023) >> 6;
                const int d0  = col & 63;
                float* dst = (sel == 0) ? g_Q : (sel == 1) ? g_K : g_V;
                const int bb = row >> 11;
                const int t  = row & (NT - 1);
                float* p = dst + (((size_t)(bb * NH + h) * NT + t) * ND + d0);
                *(float2*)p = v0;
                *(float2*)(p + 8*ND) = v1;          // row+8 -> t+8
            } else {
                float* p = Cout + (size_t)row * NC + col;
                *(float2*)p = v0;
                *(float2*)(p + 8*NC) = v1;
            }
        }
    }
}

// ---------------------------------------------------------------------------
// Causal flash attention (round-1 version). grid=(T/128, B*H), 128 threads.
// ---------------------------------------------------------------------------
__global__ __launch_bounds__(128) void attn_kernel()
{
    __shared__ float Ks[64][64];
    __shared__ float Vs[64][64];

    const int qt  = blockIdx.x;
    const int bh  = blockIdx.y;
    const int tid = threadIdx.x;
    const int r   = qt * 128 + tid;

    const float* Qp = g_Q + (size_t)bh * NT * ND;
    const float* Kp = g_K + (size_t)bh * NT * ND;
    const float* Vp = g_V + (size_t)bh * NT * ND;

    const float scale = 0.125f;

    float q[64];
    {
        const float4* qr = (const float4*)(Qp + (size_t)r * ND);
        #pragma unroll
        for (int k4 = 0; k4 < 16; k4++) {
            float4 v = qr[k4];
            q[k4*4+0] = v.x * scale; q[k4*4+1] = v.y * scale;
            q[k4*4+2] = v.z * scale; q[k4*4+3] = v.w * scale;
        }
    }

    float m_ = neg_inf();
    float l  = 0.f;
    float o[64];
    #pragma unroll
    for (int d = 0; d < 64; d++) o[d] = 0.f;

    const int kend = qt * 128 + 128;

    for (int kt = 0; kt < kend; kt += 64) {
        __syncthreads();
        {
            const float4* kg = (const float4*)(Kp + (size_t)kt * ND);
            const float4* vg = (const float4*)(Vp + (size_t)kt * ND);
            float4* ks = (float4*)&Ks[0][0];
            float4* vs = (float4*)&Vs[0][0];
            #pragma unroll
            for (int i = 0; i < 8; i++) {
                int idx = tid + 128 * i;
                ks[idx] = kg[idx];
                vs[idx] = vg[idx];
            }
        }
        __syncthreads();

        #pragma unroll
        for (int jt = 0; jt < 64; jt += 16) {
            float s[16];
            #pragma unroll
            for (int j = 0; j < 16; j++) {
                const float4* kr = (const float4*)&Ks[jt + j][0];
                float a = 0.f;
                #pragma unroll
                for (int k4 = 0; k4 < 16; k4++) {
                    float4 kv = kr[k4];
                    a = fmaf(q[k4*4+0], kv.x, a);
                    a = fmaf(q[k4*4+1], kv.y, a);
                    a = fmaf(q[k4*4+2], kv.z, a);
                    a = fmaf(q[k4*4+3], kv.w, a);
                }
                int jg = kt + jt + j;
                s[j] = (jg <= r) ? a : neg_inf();
            }
            float tmax = s[0];
            #pragma unroll
            for (int j = 1; j < 16; j++) tmax = fmaxf(tmax, s[j]);
            float mnew = fmaxf(m_, tmax);
            float sc = __expf(m_ - mnew);
            l *= sc;
            #pragma unroll
            for (int d = 0; d < 64; d++) o[d] *= sc;
            m_ = mnew;
            #pragma unroll
            for (int j = 0; j < 16; j++) {
                float p = __expf(s[j] - mnew);
                l += p;
                const float4* vr = (const float4*)&Vs[jt + j][0];
                #pragma unroll
                for (int d4 = 0; d4 < 16; d4++) {
                    float4 vv = vr[d4];
                    o[d4*4+0] = fmaf(p, vv.x, o[d4*4+0]);
                    o[d4*4+1] = fmaf(p, vv.y, o[d4*4+1]);
                    o[d4*4+2] = fmaf(p, vv.z, o[d4*4+2]);
                    o[d4*4+3] = fmaf(p, vv.w, o[d4*4+3]);
                }
            }
        }
    }

    const float inv = 1.0f / l;
    const int b = bh >> 4;
    const int h = bh & 15;
    float* p = g_AO + ((size_t)(b * NT + r)) * NC + h * ND;
    #pragma unroll
    for (int d4 = 0; d4 < 16; d4++) {
        float4 v = make_float4(o[d4*4+0]*inv, o[d4*4+1]*inv,
                               o[d4*4+2]*inv, o[d4*4+3]*inv);
        ((float4*)p)[d4] = v;
    }
}

// ---------------------------------------------------------------------------
extern "C" void kernel_launch(void* const* d_in, const int* in_sizes, int n_in,
                              void* d_out, int out_size)
{
    const float* x     = (const float*)d_in[0];
    const float* Wqkv  = (const float*)d_in[1];
    const float* bqkv  = (const float*)d_in[2];
    const float* Wout  = (const float*)d_in[3];
    const float* bout  = (const float*)d_in[4];
    float* out = (float*)d_out;

    static int cfg_done = 0;
    if (!cfg_done) {
        cudaFuncSetAttribute(gemm_mma<0>, cudaFuncAttributeMaxDynamicSharedMemorySize, GEMM_SMEM);
        cudaFuncSetAttribute(gemm_mma<1>, cudaFuncAttributeMaxDynamicSharedMemorySize, GEMM_SMEM);
        cfg_done = 1;
    }

    gemm_mma<0><<<dim3(N_QKV/BN, NM/BM), 256, GEMM_SMEM>>>(x, Wqkv, bqkv, nullptr);
    attn_kernel<<<dim3(NT/128, NB*NH), 128>>>();
    gemm_mma<1><<<dim3(NC/BN, NM/BM), 256, GEMM_SMEM>>>(nullptr, Wout, bout, out);
}

// round 8
// speedup vs baseline: 4.6093x; 3.3048x over previous
#include <cuda_runtime.h>

#define NB 4
#define NT 2048
#define NC 1024
#define NH 16
#define ND 64
#define NM (NB*NT)      // 8192 rows
#define N_QKV (3*NC)    // 3072

// Scratch (device globals — no allocations allowed)
__device__ float g_Q[(size_t)NB*NH*NT*ND];
__device__ float g_K[(size_t)NB*NH*NT*ND];
__device__ float g_V[(size_t)NB*NH*NT*ND];
__device__ float g_AO[(size_t)NM*NC];

__device__ __forceinline__ unsigned smem_u32(const void* p) {
    unsigned a;
    asm("{ .reg .u64 t; cvta.to.shared.u64 t, %1; cvt.u32.u64 %0, t; }"
        : "=r"(a) : "l"(p));
    return a;
}
__device__ __forceinline__ void cp_async16(unsigned dst, const void* src) {
    asm volatile("cp.async.cg.shared.global [%0], [%1], 16;" :: "r"(dst), "l"(src));
}
#define CP_COMMIT()  asm volatile("cp.async.commit_group;" ::: "memory")
#define CP_WAIT(n)   asm volatile("cp.async.wait_group %0;" :: "n"(n) : "memory")

__device__ __forceinline__ unsigned f2tf32(float f) {
    unsigned u;
    asm("cvt.rna.tf32.f32 %0, %1;" : "=r"(u) : "f"(f));
    return u;
}
__device__ __forceinline__ float ex2f(float x) {
    float y; asm("ex2.approx.f32 %0, %1;" : "=f"(y) : "f"(x)); return y;
}
__device__ __forceinline__ void mma_tf32(float c[4], const unsigned a[4], const unsigned b[2]) {
    asm volatile(
        "mma.sync.aligned.m16n8k8.row.col.f32.tf32.tf32.f32 "
        "{%0,%1,%2,%3}, {%4,%5,%6,%7}, {%8,%9}, {%0,%1,%2,%3};"
        : "+f"(c[0]), "+f"(c[1]), "+f"(c[2]), "+f"(c[3])
        : "r"(a[0]), "r"(a[1]), "r"(a[2]), "r"(a[3]), "r"(b[0]), "r"(b[1]));
}

// ===========================================================================
// mma.sync tf32 GEMM (unchanged from round 6, passing at rel_err 3.2e-4)
// ===========================================================================
#define BM 128
#define BN 128
#define BK 16
#define SROW 20
#define STAGE_FLOATS (2*128*SROW)
#define STAGE_BYTES  (STAGE_FLOATS*4)
#define NSLAB (NC/BK)
#define GEMM_SMEM (3*STAGE_BYTES)

template<int MODE>
__device__ __forceinline__ void load_slab(const float* __restrict__ A,
                                          const float* __restrict__ W,
                                          int m0, int n0, int slab, int st,
                                          unsigned sb, int tid)
{
    const unsigned abase = sb + st * STAGE_BYTES;
    const unsigned bbase = abase + 128*SROW*4;
    const float* ag = A + (size_t)m0 * NC + slab * BK;
    const float* wg = W + (size_t)n0 * NC + slab * BK;
    #pragma unroll
    for (int i = 0; i < 2; i++) {
        int idx = tid + 256 * i;
        int row = idx >> 2, c4 = idx & 3;
        cp_async16(abase + row * (SROW*4) + c4 * 16, ag + (size_t)row * NC + c4 * 4);
    }
    #pragma unroll
    for (int i = 0; i < 2; i++) {
        int idx = tid + 256 * i;
        int row = idx >> 2, c4 = idx & 3;
        cp_async16(bbase + row * (SROW*4) + c4 * 16, wg + (size_t)row * NC + c4 * 4);
    }
    CP_COMMIT();
}

template<int MODE>
__global__ __launch_bounds__(256) void gemm_mma(
    const float* __restrict__ Ain, const float* __restrict__ W,
    const float* __restrict__ bias, float* __restrict__ Cout)
{
    extern __shared__ float smem[];
    const unsigned sb = smem_u32(smem);
    const int tid  = threadIdx.x;
    const int wid  = tid >> 5, lane = tid & 31;
    const int wm   = wid >> 2;
    const int wn   = wid & 3;
    const int m0   = blockIdx.y * BM;
    const int n0   = blockIdx.x * BN;
    const float* A = (MODE == 0) ? Ain : g_AO;

    const int lr = lane >> 2;
    const int lc = lane & 3;

    float acc[4][4][4];
    #pragma unroll
    for (int mt = 0; mt < 4; mt++)
        #pragma unroll
        for (int nt = 0; nt < 4; nt++)
            #pragma unroll
            for (int i = 0; i < 4; i++) acc[mt][nt][i] = 0.f;

    load_slab<MODE>(A, W, m0, n0, 0, 0, sb, tid);
    load_slab<MODE>(A, W, m0, n0, 1, 1, sb, tid);
    load_slab<MODE>(A, W, m0, n0, 2, 2, sb, tid);

    for (int i = 0; i < NSLAB; i++) {
        const int st = i % 3;
        const int rem = NSLAB - 1 - i;
        if (rem >= 2)      CP_WAIT(2);
        else if (rem == 1) CP_WAIT(1);
        else               CP_WAIT(0);
        __syncthreads();

        const float* As = smem + st * STAGE_FLOATS;
        const float* Bs = As + 128*SROW;

        #pragma unroll
        for (int ks = 0; ks < 2; ks++) {
            unsigned a[4][4], b[4][2];
            #pragma unroll
            for (int mt = 0; mt < 4; mt++) {
                const float* p = As + (wm*64 + mt*16 + lr) * SROW + ks*8 + lc;
                a[mt][0] = f2tf32(p[0]);
                a[mt][1] = f2tf32(p[8*SROW]);
                a[mt][2] = f2tf32(p[4]);
                a[mt][3] = f2tf32(p[8*SROW + 4]);
            }
            #pragma unroll
            for (int nt = 0; nt < 4; nt++) {
                const float* p = Bs + (wn*32 + nt*8 + lr) * SROW + ks*8 + lc;
                b[nt][0] = f2tf32(p[0]);
                b[nt][1] = f2tf32(p[4]);
            }
            #pragma unroll
            for (int mt = 0; mt < 4; mt++)
                #pragma unroll
                for (int nt = 0; nt < 4; nt++)
                    mma_tf32(acc[mt][nt], a[mt], b[nt]);
        }
        __syncthreads();

        if (i + 3 < NSLAB)
            load_slab<MODE>(A, W, m0, n0, i + 3, st, sb, tid);
    }

    #pragma unroll
    for (int mt = 0; mt < 4; mt++) {
        const int row = m0 + wm*64 + mt*16 + lr;
        #pragma unroll
        for (int nt = 0; nt < 4; nt++) {
            const int col = n0 + wn*32 + nt*8 + 2*lc;
            const float b0 = bias[col], b1 = bias[col + 1];
            float2 v0 = make_float2(acc[mt][nt][0] + b0, acc[mt][nt][1] + b1);
            float2 v1 = make_float2(acc[mt][nt][2] + b0, acc[mt][nt][3] + b1);
            if (MODE == 0) {
                const int sel = col >> 10;
                const int h   = (col & 1023) >> 6;
                const int d0  = col & 63;
                float* dst = (sel == 0) ? g_Q : (sel == 1) ? g_K : g_V;
                const int bb = row >> 11;
                const int t  = row & (NT - 1);
                float* p = dst + (((size_t)(bb * NH + h) * NT + t) * ND + d0);
                *(float2*)p = v0;
                *(float2*)(p + 8*ND) = v1;
            } else {
                float* p = Cout + (size_t)row * NC + col;
                *(float2*)p = v0;
                *(float2*)(p + 8*NC) = v1;
            }
        }
    }
}

// ===========================================================================
// Flash attention with mma.sync tf32.
// grid = (32 q-tiles, 64 bh), 128 threads (4 warps), warp = 16 query rows.
// Online softmax in log2 domain (Q pre-scaled by 0.125*log2e, ex2.approx).
// P routed through per-warp padded SMEM slab to form A-fragments for P·V.
// K/P stride 68, V stride 72 -> conflict-free fragment gathers.
// ===========================================================================
#define SKV_K 68
#define SKV_V 72
#define A_KOFF 0
#define A_KSZ (64*SKV_K)             // 4352 floats
#define A_VOFF (2*A_KSZ)             // 8704
#define A_VSZ (64*SKV_V)             // 4608
#define A_POFF (A_VOFF + 2*A_VSZ)    // 17920
#define A_PSZ (16*SKV_K)             // 1088
#define ATTN_SMEM ((A_POFF + 4*A_PSZ)*4)   // 89088 B

__device__ __forceinline__ void attn_load_kv(const float* Kt, const float* Vt,
                                             unsigned kb, unsigned vb, int tid)
{
    #pragma unroll
    for (int i = 0; i < 8; i++) {
        int idx = tid + 128*i;
        int row = idx >> 4, c4 = idx & 15;
        cp_async16(kb + row*(SKV_K*4) + c4*16, Kt + (size_t)row*ND + c4*4);
    }
    #pragma unroll
    for (int i = 0; i < 8; i++) {
        int idx = tid + 128*i;
        int row = idx >> 4, c4 = idx & 15;
        cp_async16(vb + row*(SKV_V*4) + c4*16, Vt + (size_t)row*ND + c4*4);
    }
}

__global__ __launch_bounds__(128) void attn_mma()
{
    extern __shared__ float sm[];
    const unsigned sb = smem_u32(sm);
    const int tid = threadIdx.x, wid = tid >> 5, lane = tid & 31;
    const int lr = lane >> 2, lc = lane & 3;
    const int qt = (int)gridDim.x - 1 - (int)blockIdx.x;   // heavy tiles first
    const int bh = blockIdx.y;
    const int q0 = qt * 64;
    const int nkt = qt + 1;

    const float* Qp = g_Q + (size_t)bh * NT * ND;
    const float* Kp = g_K + (size_t)bh * NT * ND;
    const float* Vp = g_V + (size_t)bh * NT * ND;

    // Q tile (64x64) -> P region (stride 68), plus K/V tile 0 -> stage 0
    #pragma unroll
    for (int i = 0; i < 8; i++) {
        int idx = tid + 128*i;
        int row = idx >> 4, c4 = idx & 15;
        cp_async16(sb + (A_POFF + row*SKV_K)*4 + c4*16,
                   Qp + (size_t)(q0 + row)*ND + c4*4);
    }
    attn_load_kv(Kp, Vp, sb + A_KOFF*4, sb + A_VOFF*4, tid);
    CP_COMMIT();
    CP_WAIT(0);
    __syncthreads();

    // Q fragments, pre-scaled by 1/sqrt(64) * log2(e)  (softmax in log2 domain)
    const float qsc = 0.125f * 1.44269504f;
    unsigned qa[8][4];
    {
        const float* Pq = sm + A_POFF + (wid*16)*SKV_K;   // own 16-row slab only
        #pragma unroll
        for (int k0 = 0; k0 < 8; k0++) {
            qa[k0][0] = f2tf32(Pq[(lr  )*SKV_K + k0*8 + lc    ] * qsc);
            qa[k0][1] = f2tf32(Pq[(lr+8)*SKV_K + k0*8 + lc    ] * qsc);
            qa[k0][2] = f2tf32(Pq[(lr  )*SKV_K + k0*8 + lc + 4] * qsc);
            qa[k0][3] = f2tf32(Pq[(lr+8)*SKV_K + k0*8 + lc + 4] * qsc);
        }
    }

    float m0 = -1e30f, m1 = -1e30f, l0 = 0.f, l1 = 0.f;
    float o[8][4];
    #pragma unroll
    for (int nt = 0; nt < 8; nt++) { o[nt][0]=o[nt][1]=o[nt][2]=o[nt][3]=0.f; }

    float* Pw = sm + A_POFF + wid*A_PSZ;

    for (int kt = 0; kt < nkt; kt++) {
        const int st = kt & 1;
        CP_WAIT(0);
        __syncthreads();
        if (kt + 1 < nkt) {
            attn_load_kv(Kp + (size_t)(kt+1)*64*ND, Vp + (size_t)(kt+1)*64*ND,
                         sb + (A_KOFF + (st^1)*A_KSZ)*4,
                         sb + (A_VOFF + (st^1)*A_VSZ)*4, tid);
            CP_COMMIT();
        }

        const float* Ks = sm + A_KOFF + st*A_KSZ;
        const float* Vs = sm + A_VOFF + st*A_VSZ;

        // S = Q * K^T   (per warp: 16 x 64)
        float s[8][4];
        #pragma unroll
        for (int nt = 0; nt < 8; nt++) { s[nt][0]=s[nt][1]=s[nt][2]=s[nt][3]=0.f; }
        #pragma unroll
        for (int nt = 0; nt < 8; nt++) {
            #pragma unroll
            for (int k0 = 0; k0 < 8; k0++) {
                unsigned b[2];
                b[0] = f2tf32(Ks[(nt*8 + lr)*SKV_K + k0*8 + lc    ]);
                b[1] = f2tf32(Ks[(nt*8 + lr)*SKV_K + k0*8 + lc + 4]);
                mma_tf32(s[nt], qa[k0], b);
            }
        }

        // causal mask: only the diagonal tile needs it (kt*64 == q0)
        if (kt == qt) {
            const int r0l = wid*16 + lr;
            #pragma unroll
            for (int nt = 0; nt < 8; nt++) {
                const int c0 = nt*8 + 2*lc;
                if (c0     > r0l    ) s[nt][0] = -1e30f;
                if (c0 + 1 > r0l    ) s[nt][1] = -1e30f;
                if (c0     > r0l + 8) s[nt][2] = -1e30f;
                if (c0 + 1 > r0l + 8) s[nt][3] = -1e30f;
            }
        }

        // online softmax (log2 domain)
        float tm0 = -1e30f, tm1 = -1e30f;
        #pragma unroll
        for (int nt = 0; nt < 8; nt++) {
            tm0 = fmaxf(tm0, fmaxf(s[nt][0], s[nt][1]));
            tm1 = fmaxf(tm1, fmaxf(s[nt][2], s[nt][3]));
        }
        tm0 = fmaxf(tm0, __shfl_xor_sync(0xffffffffu, tm0, 1));
        tm0 = fmaxf(tm0, __shfl_xor_sync(0xffffffffu, tm0, 2));
        tm1 = fmaxf(tm1, __shfl_xor_sync(0xffffffffu, tm1, 1));
        tm1 = fmaxf(tm1, __shfl_xor_sync(0xffffffffu, tm1, 2));

        const float mn0 = fmaxf(m0, tm0), mn1 = fmaxf(m1, tm1);
        const float sc0 = ex2f(m0 - mn0), sc1 = ex2f(m1 - mn1);
        m0 = mn0; m1 = mn1;

        float rs0 = 0.f, rs1 = 0.f;
        #pragma unroll
        for (int nt = 0; nt < 8; nt++) {
            float p0 = ex2f(s[nt][0] - mn0);
            float p1 = ex2f(s[nt][1] - mn0);
            float p2 = ex2f(s[nt][2] - mn1);
            float p3 = ex2f(s[nt][3] - mn1);
            rs0 += p0 + p1;
            rs1 += p2 + p3;
            *(float2*)&Pw[(lr  )*SKV_K + nt*8 + 2*lc] = make_float2(p0, p1);
            *(float2*)&Pw[(lr+8)*SKV_K + nt*8 + 2*lc] = make_float2(p2, p3);
        }
        rs0 += __shfl_xor_sync(0xffffffffu, rs0, 1);
        rs0 += __shfl_xor_sync(0xffffffffu, rs0, 2);
        rs1 += __shfl_xor_sync(0xffffffffu, rs1, 1);
        rs1 += __shfl_xor_sync(0xffffffffu, rs1, 2);
        l0 = l0*sc0 + rs0;
        l1 = l1*sc1 + rs1;
        #pragma unroll
        for (int nt = 0; nt < 8; nt++) {
            o[nt][0] *= sc0; o[nt][1] *= sc0;
            o[nt][2] *= sc1; o[nt][3] *= sc1;
        }
        __syncwarp();

        // O += P * V
        #pragma unroll
        for (int k0 = 0; k0 < 8; k0++) {
            unsigned a[4];
            a[0] = f2tf32(Pw[(lr  )*SKV_K + k0*8 + lc    ]);
            a[1] = f2tf32(Pw[(lr+8)*SKV_K + k0*8 + lc    ]);
            a[2] = f2tf32(Pw[(lr  )*SKV_K + k0*8 + lc + 4]);
            a[3] = f2tf32(Pw[(lr+8)*SKV_K + k0*8 + lc + 4]);
            #pragma unroll
            for (int nt = 0; nt < 8; nt++) {
                unsigned b[2];
                b[0] = f2tf32(Vs[(k0*8 + lc    )*SKV_V + nt*8 + lr]);
                b[1] = f2tf32(Vs[(k0*8 + lc + 4)*SKV_V + nt*8 + lr]);
                mma_tf32(o[nt], a, b);
            }
        }
    }

    // epilogue: normalize, scatter to g_AO[b][t][h*64+d]
    const float inv0 = 1.f / l0, inv1 = 1.f / l1;
    const int b = bh >> 4, h = bh & 15;
    const int r0 = q0 + wid*16 + lr, r1 = r0 + 8;
    #pragma unroll
    for (int nt = 0; nt < 8; nt++) {
        const int col = nt*8 + 2*lc;
        *(float2*)&g_AO[((size_t)(b*NT + r0))*NC + h*ND + col] =
            make_float2(o[nt][0]*inv0, o[nt][1]*inv0);
        *(float2*)&g_AO[((size_t)(b*NT + r1))*NC + h*ND + col] =
            make_float2(o[nt][2]*inv1, o[nt][3]*inv1);
    }
}

// ---------------------------------------------------------------------------
extern "C" void kernel_launch(void* const* d_in, const int* in_sizes, int n_in,
                              void* d_out, int out_size)
{
    const float* x     = (const float*)d_in[0];
    const float* Wqkv  = (const float*)d_in[1];
    const float* bqkv  = (const float*)d_in[2];
    const float* Wout  = (const float*)d_in[3];
    const float* bout  = (const float*)d_in[4];
    float* out = (float*)d_out;

    static int cfg_done = 0;
    if (!cfg_done) {
        cudaFuncSetAttribute(gemm_mma<0>, cudaFuncAttributeMaxDynamicSharedMemorySize, GEMM_SMEM);
        cudaFuncSetAttribute(gemm_mma<1>, cudaFuncAttributeMaxDynamicSharedMemorySize, GEMM_SMEM);
        cudaFuncSetAttribute(attn_mma,    cudaFuncAttributeMaxDynamicSharedMemorySize, ATTN_SMEM);
        cfg_done = 1;
    }

    gemm_mma<0><<<dim3(N_QKV/BN, NM/BM), 256, GEMM_SMEM>>>(x, Wqkv, bqkv, nullptr);
    attn_mma<<<dim3(NT/64, NB*NH), 128, ATTN_SMEM>>>();
    gemm_mma<1><<<dim3(NC/BN, NM/BM), 256, GEMM_SMEM>>>(nullptr, Wout, bout, out);
}

// round 10
// speedup vs baseline: 5.0002x; 1.0848x over previous
#include <cuda_runtime.h>

#define NB 4
#define NT 2048
#define NC 1024
#define NH 16
#define ND 64
#define NM (NB*NT)      // 8192 rows
#define N_QKV (3*NC)    // 3072

// Scratch (device globals — no allocations allowed)
__device__ float g_Q[(size_t)NB*NH*NT*ND];
__device__ float g_K[(size_t)NB*NH*NT*ND];
__device__ float g_V[(size_t)NB*NH*NT*ND];
__device__ float g_AO[(size_t)NM*NC];
__device__ float g_xr[(size_t)NM*NC];        // tf32-rounded x
__device__ float g_Wq[(size_t)N_QKV*NC];     // tf32-rounded W_qkv
__device__ float g_Wo[(size_t)NC*NC];        // tf32-rounded W_out

__device__ __forceinline__ unsigned smem_u32(const void* p) {
    unsigned a;
    asm("{ .reg .u64 t; cvta.to.shared.u64 t, %1; cvt.u32.u64 %0, t; }"
        : "=r"(a) : "l"(p));
    return a;
}
__device__ __forceinline__ void cp_async16(unsigned dst, const void* src) {
    asm volatile("cp.async.cg.shared.global [%0], [%1], 16;" :: "r"(dst), "l"(src));
}
#define CP_COMMIT()  asm volatile("cp.async.commit_group;" ::: "memory")
#define CP_WAIT(n)   asm volatile("cp.async.wait_group %0;" :: "n"(n) : "memory")

__device__ __forceinline__ unsigned f2tf32(float f) {
    unsigned u;
    asm("cvt.rna.tf32.f32 %0, %1;" : "=r"(u) : "f"(f));
    return u;
}
__device__ __forceinline__ float rnd_tf32(float f) { return __uint_as_float(f2tf32(f)); }
__device__ __forceinline__ float ex2f(float x) {
    float y; asm("ex2.approx.f32 %0, %1;" : "=f"(y) : "f"(x)); return y;
}
__device__ __forceinline__ void mma_tf32(float c[4], const unsigned a[4], const unsigned b[2]) {
    asm volatile(
        "mma.sync.aligned.m16n8k8.row.col.f32.tf32.tf32.f32 "
        "{%0,%1,%2,%3}, {%4,%5,%6,%7}, {%8,%9}, {%0,%1,%2,%3};"
        : "+f"(c[0]), "+f"(c[1]), "+f"(c[2]), "+f"(c[3])
        : "r"(a[0]), "r"(a[1]), "r"(a[2]), "r"(a[3]), "r"(b[0]), "r"(b[1]));
}

// ===========================================================================
// Pre-round pass: y = tf32_round(x), float4 grid-stride.
// ===========================================================================
__global__ __launch_bounds__(256) void round_pass(const float4* __restrict__ in,
                                                  float4* __restrict__ out, int n4)
{
    int i = blockIdx.x * blockDim.x + threadIdx.x;
    const int stride = gridDim.x * blockDim.x;
    for (; i < n4; i += stride) {
        float4 v = in[i];
        v.x = rnd_tf32(v.x); v.y = rnd_tf32(v.y);
        v.z = rnd_tf32(v.z); v.w = rnd_tf32(v.w);
        out[i] = v;
    }
}

// ===========================================================================
// mma.sync tf32 GEMM. Inputs pre-rounded to tf32 -> raw LDS feeds MMA (no cvt).
// CTA tile 128x128, BK=16, 256 threads (8 warps 2x4), 3-stage cp.async.
// MODE 0: scatter rounded outputs into g_Q/g_K/g_V.  MODE 1: plain store.
// ===========================================================================
#define BM 128
#define BN 128
#define BK 16
#define SROW 20
#define STAGE_FLOATS (2*128*SROW)
#define STAGE_BYTES  (STAGE_FLOATS*4)
#define NSLAB (NC/BK)
#define GEMM_SMEM (3*STAGE_BYTES)

__device__ __forceinline__ void load_slab(const float* __restrict__ A,
                                          const float* __restrict__ W,
                                          int m0, int n0, int slab, int st,
                                          unsigned sb, int tid)
{
    const unsigned abase = sb + st * STAGE_BYTES;
    const unsigned bbase = abase + 128*SROW*4;
    const float* ag = A + (size_t)m0 * NC + slab * BK;
    const float* wg = W + (size_t)n0 * NC + slab * BK;
    #pragma unroll
    for (int i = 0; i < 2; i++) {
        int idx = tid + 256 * i;
        int row = idx >> 2, c4 = idx & 3;
        cp_async16(abase + row * (SROW*4) + c4 * 16, ag + (size_t)row * NC + c4 * 4);
    }
    #pragma unroll
    for (int i = 0; i < 2; i++) {
        int idx = tid + 256 * i;
        int row = idx >> 2, c4 = idx & 3;
        cp_async16(bbase + row * (SROW*4) + c4 * 16, wg + (size_t)row * NC + c4 * 4);
    }
    CP_COMMIT();
}

template<int MODE>
__global__ __launch_bounds__(256) void gemm_mma(
    const float* __restrict__ A, const float* __restrict__ W,
    const float* __restrict__ bias, float* __restrict__ Cout)
{
    extern __shared__ float smem[];
    const unsigned sb = smem_u32(smem);
    const int tid  = threadIdx.x;
    const int wid  = tid >> 5, lane = tid & 31;
    const int wm   = wid >> 2;
    const int wn   = wid & 3;
    const int m0   = blockIdx.y * BM;
    const int n0   = blockIdx.x * BN;

    const int lr = lane >> 2;
    const int lc = lane & 3;

    float acc[4][4][4];
    #pragma unroll
    for (int mt = 0; mt < 4; mt++)
        #pragma unroll
        for (int nt = 0; nt < 4; nt++)
            #pragma unroll
            for (int i = 0; i < 4; i++) acc[mt][nt][i] = 0.f;

    load_slab(A, W, m0, n0, 0, 0, sb, tid);
    load_slab(A, W, m0, n0, 1, 1, sb, tid);
    load_slab(A, W, m0, n0, 2, 2, sb, tid);

    for (int i = 0; i < NSLAB; i++) {
        const int st = i % 3;
        const int rem = NSLAB - 1 - i;
        if (rem >= 2)      CP_WAIT(2);
        else if (rem == 1) CP_WAIT(1);
        else               CP_WAIT(0);
        __syncthreads();

        const unsigned* As = (const unsigned*)(smem + st * STAGE_FLOATS);
        const unsigned* Bs = As + 128*SROW;

        #pragma unroll
        for (int ks = 0; ks < 2; ks++) {
            unsigned a[4][4], b[4][2];
            #pragma unroll
            for (int mt = 0; mt < 4; mt++) {
                const unsigned* p = As + (wm*64 + mt*16 + lr) * SROW + ks*8 + lc;
                a[mt][0] = p[0];
                a[mt][1] = p[8*SROW];
                a[mt][2] = p[4];
                a[mt][3] = p[8*SROW + 4];
            }
            #pragma unroll
            for (int nt = 0; nt < 4; nt++) {
                const unsigned* p = Bs + (wn*32 + nt*8 + lr) * SROW + ks*8 + lc;
                b[nt][0] = p[0];
                b[nt][1] = p[4];
            }
            #pragma unroll
            for (int mt = 0; mt < 4; mt++)
                #pragma unroll
                for (int nt = 0; nt < 4; nt++)
                    mma_tf32(acc[mt][nt], a[mt], b[nt]);
        }
        __syncthreads();

        if (i + 3 < NSLAB)
            load_slab(A, W, m0, n0, i + 3, st, sb, tid);
    }

    #pragma unroll
    for (int mt = 0; mt < 4; mt++) {
        const int row = m0 + wm*64 + mt*16 + lr;
        #pragma unroll
        for (int nt = 0; nt < 4; nt++) {
            const int col = n0 + wn*32 + nt*8 + 2*lc;
            const float b0 = bias[col], b1 = bias[col + 1];
            if (MODE == 0) {
                // rounded store: attention consumes these as tf32 operands
                float2 v0 = make_float2(rnd_tf32(acc[mt][nt][0] + b0),
                                        rnd_tf32(acc[mt][nt][1] + b1));
                float2 v1 = make_float2(rnd_tf32(acc[mt][nt][2] + b0),
                                        rnd_tf32(acc[mt][nt][3] + b1));
                const int sel = col >> 10;
                const int h   = (col & 1023) >> 6;
                const int d0  = col & 63;
                float* dst = (sel == 0) ? g_Q : (sel == 1) ? g_K : g_V;
                const int bb = row >> 11;
                const int t  = row & (NT - 1);
                float* p = dst + (((size_t)(bb * NH + h) * NT + t) * ND + d0);
                *(float2*)p = v0;
                *(float2*)(p + 8*ND) = v1;
            } else {
                float2 v0 = make_float2(acc[mt][nt][0] + b0, acc[mt][nt][1] + b1);
                float2 v1 = make_float2(acc[mt][nt][2] + b0, acc[mt][nt][3] + b1);
                float* p = Cout + (size_t)row * NC + col;
                *(float2*)p = v0;
                *(float2*)(p + 8*NC) = v1;
            }
        }
    }
}

// ===========================================================================
// Flash attention, mma.sync tf32, q-tile 128 (8 warps x 16 rows, 256 thr).
// K/V tiles 64 rows, double-buffered cp.async. All operands pre-rounded ->
// raw LDS feeds MMA. Softmax in log2 domain. P rounded at store-side.
// ===========================================================================
#define SKV_K 68
#define SKV_V 72
#define A_KOFF 0
#define A_KSZ (64*SKV_K)                  // 4352 floats
#define A_VOFF (2*A_KSZ)                  // 8704
#define A_VSZ (64*SKV_V)                  // 4608
#define A_QPOFF (A_VOFF + 2*A_VSZ)        // 17920
#define A_QPSZ (128*SKV_K)                // 8704 floats
#define ATTN_SMEM ((A_QPOFF + A_QPSZ)*4)  // 106496 B

__device__ __forceinline__ void attn_load_kv(const float* Kt, const float* Vt,
                                             unsigned kb, unsigned vb, int tid)
{
    #pragma unroll
    for (int i = 0; i < 4; i++) {         // K: 64 rows x 16 f4 = 1024 f4
        int idx = tid + 256*i;
        int row = idx >> 4, c4 = idx & 15;
        cp_async16(kb + row*(SKV_K*4) + c4*16, Kt + (size_t)row*ND + c4*4);
    }
    #pragma unroll
    for (int i = 0; i < 4; i++) {
        int idx = tid + 256*i;
        int row = idx >> 4, c4 = idx & 15;
        cp_async16(vb + row*(SKV_V*4) + c4*16, Vt + (size_t)row*ND + c4*4);
    }
}

__global__ __launch_bounds__(256) void attn_mma()
{
    extern __shared__ float sm[];
    const unsigned sb = smem_u32(sm);
    const int tid = threadIdx.x, wid = tid >> 5, lane = tid & 31;
    const int lr = lane >> 2, lc = lane & 3;
    const int qt = (int)gridDim.x - 1 - (int)blockIdx.x;   // heavy tiles first
    const int bh = blockIdx.y;
    const int q0 = qt * 128;
    const int nkt = 2*qt + 2;

    const float* Qp = g_Q + (size_t)bh * NT * ND;
    const float* Kp = g_K + (size_t)bh * NT * ND;
    const float* Vp = g_V + (size_t)bh * NT * ND;

    // Q tile (128x64) -> QP region (stride 68); K/V tile 0 -> stage 0
    #pragma unroll
    for (int i = 0; i < 8; i++) {         // 128 rows x 16 f4 = 2048 f4
        int idx = tid + 256*i;
        int row = idx >> 4, c4 = idx & 15;
        cp_async16(sb + (A_QPOFF + row*SKV_K)*4 + c4*16,
                   Qp + (size_t)(q0 + row)*ND + c4*4);
    }
    attn_load_kv(Kp, Vp, sb + A_KOFF*4, sb + A_VOFF*4, tid);
    CP_COMMIT();
    CP_WAIT(0);
    __syncthreads();

    // Q fragments, pre-scaled by 1/8 * log2(e); re-round after scaling
    const float qsc = 0.125f * 1.44269504f;
    unsigned qa[8][4];
    {
        const float* Pq = sm + A_QPOFF + (wid*16)*SKV_K;
        #pragma unroll
        for (int k0 = 0; k0 < 8; k0++) {
            qa[k0][0] = f2tf32(Pq[(lr  )*SKV_K + k0*8 + lc    ] * qsc);
            qa[k0][1] = f2tf32(Pq[(lr+8)*SKV_K + k0*8 + lc    ] * qsc);
            qa[k0][2] = f2tf32(Pq[(lr  )*SKV_K + k0*8 + lc + 4] * qsc);
            qa[k0][3] = f2tf32(Pq[(lr+8)*SKV_K + k0*8 + lc + 4] * qsc);
        }
    }
    __syncwarp();      // all Q reads in this warp's slab done before P overwrites

    float m0 = -1e30f, m1 = -1e30f, l0 = 0.f, l1 = 0.f;
    float o[8][4];
    #pragma unroll
    for (int nt = 0; nt < 8; nt++) { o[nt][0]=o[nt][1]=o[nt][2]=o[nt][3]=0.f; }

    float* Pw = sm + A_QPOFF + (wid*16)*SKV_K;

    for (int kt = 0; kt < nkt; kt++) {
        const int st = kt & 1;
        CP_WAIT(0);
        __syncthreads();
        if (kt + 1 < nkt) {
            attn_load_kv(Kp + (size_t)(kt+1)*64*ND, Vp + (size_t)(kt+1)*64*ND,
                         sb + (A_KOFF + (st^1)*A_KSZ)*4,
                         sb + (A_VOFF + (st^1)*A_VSZ)*4, tid);
            CP_COMMIT();
        }

        const unsigned* Ks = (const unsigned*)(sm + A_KOFF + st*A_KSZ);
        const float*    Vs = sm + A_VOFF + st*A_VSZ;

        // S = Q * K^T   (per warp: 16 x 64)
        float s[8][4];
        #pragma unroll
        for (int nt = 0; nt < 8; nt++) { s[nt][0]=s[nt][1]=s[nt][2]=s[nt][3]=0.f; }
        #pragma unroll
        for (int nt = 0; nt < 8; nt++) {
            #pragma unroll
            for (int k0 = 0; k0 < 8; k0++) {
                unsigned b[2];
                b[0] = Ks[(nt*8 + lr)*SKV_K + k0*8 + lc    ];
                b[1] = Ks[(nt*8 + lr)*SKV_K + k0*8 + lc + 4];
                mma_tf32(s[nt], qa[k0], b);
            }
        }

        // causal mask for the diagonal band (last two k-tiles)
        if (kt >= 2*qt) {
            const int r0g = q0 + wid*16 + lr;
            #pragma unroll
            for (int nt = 0; nt < 8; nt++) {
                const int c0 = kt*64 + nt*8 + 2*lc;
                if (c0     > r0g    ) s[nt][0] = -1e30f;
                if (c0 + 1 > r0g    ) s[nt][1] = -1e30f;
                if (c0     > r0g + 8) s[nt][2] = -1e30f;
                if (c0 + 1 > r0g + 8) s[nt][3] = -1e30f;
            }
        }

        // online softmax (log2 domain)
        float tm0 = -1e30f, tm1 = -1e30f;
        #pragma unroll
        for (int nt = 0; nt < 8; nt++) {
            tm0 = fmaxf(tm0, fmaxf(s[nt][0], s[nt][1]));
            tm1 = fmaxf(tm1, fmaxf(s[nt][2], s[nt][3]));
        }
        tm0 = fmaxf(tm0, __shfl_xor_sync(0xffffffffu, tm0, 1));
        tm0 = fmaxf(tm0, __shfl_xor_sync(0xffffffffu, tm0, 2));
        tm1 = fmaxf(tm1, __shfl_xor_sync(0xffffffffu, tm1, 1));
        tm1 = fmaxf(tm1, __shfl_xor_sync(0xffffffffu, tm1, 2));

        const float mn0 = fmaxf(m0, tm0), mn1 = fmaxf(m1, tm1);
        const float sc0 = ex2f(m0 - mn0), sc1 = ex2f(m1 - mn1);
        m0 = mn0; m1 = mn1;

        float rs0 = 0.f, rs1 = 0.f;
        #pragma unroll
        for (int nt = 0; nt < 8; nt++) {
            float p0 = ex2f(s[nt][0] - mn0);
            float p1 = ex2f(s[nt][1] - mn0);
            float p2 = ex2f(s[nt][2] - mn1);
            float p3 = ex2f(s[nt][3] - mn1);
            rs0 += p0 + p1;
            rs1 += p2 + p3;
            *(float2*)&Pw[(lr  )*SKV_K + nt*8 + 2*lc] =
                make_float2(rnd_tf32(p0), rnd_tf32(p1));
            *(float2*)&Pw[(lr+8)*SKV_K + nt*8 + 2*lc] =
                make_float2(rnd_tf32(p2), rnd_tf32(p3));
        }
        rs0 += __shfl_xor_sync(0xffffffffu, rs0, 1);
        rs0 += __shfl_xor_sync(0xffffffffu, rs0, 2);
        rs1 += __shfl_xor_sync(0xffffffffu, rs1, 1);
        rs1 += __shfl_xor_sync(0xffffffffu, rs1, 2);
        l0 = l0*sc0 + rs0;
        l1 = l1*sc1 + rs1;
        #pragma unroll
        for (int nt = 0; nt < 8; nt++) {
            o[nt][0] *= sc0; o[nt][1] *= sc0;
            o[nt][2] *= sc1; o[nt][3] *= sc1;
        }
        __syncwarp();

        // O += P * V
        const unsigned* Pu = (const unsigned*)Pw;
        #pragma unroll
        for (int k0 = 0; k0 < 8; k0++) {
            unsigned a[4];
            a[0] = Pu[(lr  )*SKV_K + k0*8 + lc    ];
            a[1] = Pu[(lr+8)*SKV_K + k0*8 + lc    ];
            a[2] = Pu[(lr  )*SKV_K + k0*8 + lc + 4];
            a[3] = Pu[(lr+8)*SKV_K + k0*8 + lc + 4];
            const unsigned* Vu = (const unsigned*)Vs;
            #pragma unroll
            for (int nt = 0; nt < 8; nt++) {
                unsigned b[2];
                b[0] = Vu[(k0*8 + lc    )*SKV_V + nt*8 + lr];
                b[1] = Vu[(k0*8 + lc + 4)*SKV_V + nt*8 + lr];
                mma_tf32(o[nt], a, b);
            }
        }
        __syncwarp();   // P slab reads done before next iteration's stores
    }

    // epilogue: normalize, round to tf32, scatter to g_AO[b][t][h*64+d]
    const float inv0 = 1.f / l0, inv1 = 1.f / l1;
    const int b = bh >> 4, h = bh & 15;
    const int r0 = q0 + wid*16 + lr, r1 = r0 + 8;
    #pragma unroll
    for (int nt = 0; nt < 8; nt++) {
        const int col = nt*8 + 2*lc;
        *(float2*)&g_AO[((size_t)(b*NT + r0))*NC + h*ND + col] =
            make_float2(rnd_tf32(o[nt][0]*inv0), rnd_tf32(o[nt][1]*inv0));
        *(float2*)&g_AO[((size_t)(b*NT + r1))*NC + h*ND + col] =
            make_float2(rnd_tf32(o[nt][2]*inv1), rnd_tf32(o[nt][3]*inv1));
    }
}

// ---------------------------------------------------------------------------
extern "C" void kernel_launch(void* const* d_in, const int* in_sizes, int n_in,
                              void* d_out, int out_size)
{
    const float* x     = (const float*)d_in[0];
    const float* Wqkv  = (const float*)d_in[1];
    const float* bqkv  = (const float*)d_in[2];
    const float* Wout  = (const float*)d_in[3];
    const float* bout  = (const float*)d_in[4];
    float* out = (float*)d_out;

    static int cfg_done = 0;
    if (!cfg_done) {
        cudaFuncSetAttribute(gemm_mma<0>, cudaFuncAttributeMaxDynamicSharedMemorySize, GEMM_SMEM);
        cudaFuncSetAttribute(gemm_mma<1>, cudaFuncAttributeMaxDynamicSharedMemorySize, GEMM_SMEM);
        cudaFuncSetAttribute(attn_mma,    cudaFuncAttributeMaxDynamicSharedMemorySize, ATTN_SMEM);
        cfg_done = 1;
    }

    // Device addresses of __device__ symbols (host-side symbol names are the
    // host shadow, NOT device pointers — that was round 9's bug).
    float *xr, *wq, *wo, *ao;
    cudaGetSymbolAddress((void**)&xr, g_xr);
    cudaGetSymbolAddress((void**)&wq, g_Wq);
    cudaGetSymbolAddress((void**)&wo, g_Wo);
    cudaGetSymbolAddress((void**)&ao, g_AO);

    round_pass<<<1184, 256>>>((const float4*)x,    (float4*)xr, NM*NC/4);
    round_pass<<<1184, 256>>>((const float4*)Wqkv, (float4*)wq, N_QKV*NC/4);
    round_pass<<<296,  256>>>((const float4*)Wout, (float4*)wo, NC*NC/4);

    gemm_mma<0><<<dim3(N_QKV/BN, NM/BM), 256, GEMM_SMEM>>>(xr, wq, bqkv, nullptr);
    attn_mma<<<dim3(NT/128, NB*NH), 256, ATTN_SMEM>>>();
    gemm_mma<1><<<dim3(NC/BN, NM/BM), 256, GEMM_SMEM>>>(ao, wo, bout, out);
}

// round 13
// speedup vs baseline: 5.3234x; 1.0646x over previous
#include <cuda_runtime.h>

#define NB 4
#define NT 2048
#define NC 1024
#define NH 16
#define ND 64
#define NM (NB*NT)      // 8192 rows
#define N_QKV (3*NC)    // 3072

// Scratch (device globals — no allocations allowed)
__device__ float g_Q[(size_t)NB*NH*NT*ND];
__device__ float g_K[(size_t)NB*NH*NT*ND];
__device__ float g_V[(size_t)NB*NH*NT*ND];
__device__ float g_AO[(size_t)NM*NC];

__device__ __forceinline__ unsigned smem_u32(const void* p) {
    unsigned a;
    asm("{ .reg .u64 t; cvta.to.shared.u64 t, %1; cvt.u32.u64 %0, t; }"
        : "=r"(a) : "l"(p));
    return a;
}
__device__ __forceinline__ void cp_async16(unsigned dst, const void* src) {
    asm volatile("cp.async.cg.shared.global [%0], [%1], 16;" :: "r"(dst), "l"(src));
}
#define CP_COMMIT()  asm volatile("cp.async.commit_group;" ::: "memory")
#define CP_WAIT(n)   asm volatile("cp.async.wait_group %0;" :: "n"(n) : "memory")

__device__ __forceinline__ unsigned f2tf32(float f) {
    unsigned u;
    asm("cvt.rna.tf32.f32 %0, %1;" : "=r"(u) : "f"(f));
    return u;
}
__device__ __forceinline__ float rnd_tf32(float f) { return __uint_as_float(f2tf32(f)); }
__device__ __forceinline__ float ex2f(float x) {
    float y; asm("ex2.approx.f32 %0, %1;" : "=f"(y) : "f"(x)); return y;
}
__device__ __forceinline__ void mma_tf32(float c[4], const unsigned a[4], const unsigned b[2]) {
    asm volatile(
        "mma.sync.aligned.m16n8k8.row.col.f32.tf32.tf32.f32 "
        "{%0,%1,%2,%3}, {%4,%5,%6,%7}, {%8,%9}, {%0,%1,%2,%3};"
        : "+f"(c[0]), "+f"(c[1]), "+f"(c[2]), "+f"(c[3])
        : "r"(a[0]), "r"(a[1]), "r"(a[2]), "r"(a[3]), "r"(b[0]), "r"(b[1]));
}

// ===========================================================================
// mma.sync tf32 GEMM, cvt-in-loop on raw fp32 inputs.
// CTA tile 128x128, BK=32, 256 threads (8 warps 2x4), 3-stage cp.async,
// prefetch distance 2, ONE __syncthreads per iteration.
// MODE 0: A=x, W=W_qkv; epilogue stores tf32-rounded into g_Q/g_K/g_V.
// MODE 1: A=g_AO (device symbol), W=W_out; plain store + bias.
// ===========================================================================
#define BM 128
#define BN 128
#define BK 32
#define SROW 36                              // 32 + 4 pad floats per row
#define STAGE_FLOATS (2*128*SROW)            // 9216
#define STAGE_BYTES  (STAGE_FLOATS*4)        // 36864
#define NSLAB (NC/BK)                        // 32
#define GEMM_SMEM (3*STAGE_BYTES)            // 110592 B -> 2 CTAs/SM

__device__ __forceinline__ void load_slab(const float* __restrict__ A,
                                          const float* __restrict__ W,
                                          int m0, int n0, int slab, int st,
                                          unsigned sb, int tid)
{
    const unsigned abase = sb + st * STAGE_BYTES;
    const unsigned bbase = abase + 128*SROW*4;
    const float* ag = A + (size_t)m0 * NC + slab * BK;
    const float* wg = W + (size_t)n0 * NC + slab * BK;
    #pragma unroll
    for (int i = 0; i < 4; i++) {            // A: 128 rows x 8 f4 = 1024 f4
        int idx = tid + 256 * i;
        int row = idx >> 3, c4 = idx & 7;
        cp_async16(abase + row * (SROW*4) + c4 * 16, ag + (size_t)row * NC + c4 * 4);
    }
    #pragma unroll
    for (int i = 0; i < 4; i++) {            // B: same
        int idx = tid + 256 * i;
        int row = idx >> 3, c4 = idx & 7;
        cp_async16(bbase + row * (SROW*4) + c4 * 16, wg + (size_t)row * NC + c4 * 4);
    }
    CP_COMMIT();
}

template<int MODE>
__global__ __launch_bounds__(256) void gemm_mma(
    const float* __restrict__ Ain, const float* __restrict__ W,
    const float* __restrict__ bias, float* __restrict__ Cout)
{
    extern __shared__ float smem[];
    const unsigned sb = smem_u32(smem);
    const int tid  = threadIdx.x;
    const int wid  = tid >> 5, lane = tid & 31;
    const int wm   = wid >> 2;               // 0..1  (64 rows)
    const int wn   = wid & 3;                // 0..3  (32 cols)
    const int m0   = blockIdx.y * BM;
    const int n0   = blockIdx.x * BN;
    const float* A = (MODE == 0) ? Ain : g_AO;   // device-side symbol for MODE 1

    const int lr = lane >> 2;
    const int lc = lane & 3;

    float acc[4][4][4];
    #pragma unroll
    for (int mt = 0; mt < 4; mt++)
        #pragma unroll
        for (int nt = 0; nt < 4; nt++)
            #pragma unroll
            for (int i = 0; i < 4; i++) acc[mt][nt][i] = 0.f;

    load_slab(A, W, m0, n0, 0, 0, sb, tid);
    load_slab(A, W, m0, n0, 1, 1, sb, tid);

    for (int i = 0; i < NSLAB; i++) {
        const int st = i % 3;
        if (i < NSLAB - 1) CP_WAIT(1);
        else               CP_WAIT(0);
        __syncthreads();                     // single barrier per iteration

        if (i + 2 < NSLAB)                   // prefetch into stage (i+2)%3,
            load_slab(A, W, m0, n0, i + 2, (i + 2) % 3, sb, tid);  // read at i-1

        const float* As = smem + st * STAGE_FLOATS;
        const float* Bs = As + 128*SROW;

        #pragma unroll
        for (int ks = 0; ks < 4; ks++) {
            unsigned a[4][4], b[4][2];
            #pragma unroll
            for (int mt = 0; mt < 4; mt++) {
                const float* p = As + (wm*64 + mt*16 + lr) * SROW + ks*8 + lc;
                a[mt][0] = f2tf32(p[0]);
                a[mt][1] = f2tf32(p[8*SROW]);
                a[mt][2] = f2tf32(p[4]);
                a[mt][3] = f2tf32(p[8*SROW + 4]);
            }
            #pragma unroll
            for (int nt = 0; nt < 4; nt++) {
                const float* p = Bs + (wn*32 + nt*8 + lr) * SROW + ks*8 + lc;
                b[nt][0] = f2tf32(p[0]);
                b[nt][1] = f2tf32(p[4]);
            }
            #pragma unroll
            for (int mt = 0; mt < 4; mt++)
                #pragma unroll
                for (int nt = 0; nt < 4; nt++)
                    mma_tf32(acc[mt][nt], a[mt], b[nt]);
        }
    }

    #pragma unroll
    for (int mt = 0; mt < 4; mt++) {
        const int row = m0 + wm*64 + mt*16 + lr;
        #pragma unroll
        for (int nt = 0; nt < 4; nt++) {
            const int col = n0 + wn*32 + nt*8 + 2*lc;
            const float b0 = bias[col], b1 = bias[col + 1];
            if (MODE == 0) {
                // rounded store: attention consumes these as raw tf32 operands
                float2 v0 = make_float2(rnd_tf32(acc[mt][nt][0] + b0),
                                        rnd_tf32(acc[mt][nt][1] + b1));
                float2 v1 = make_float2(rnd_tf32(acc[mt][nt][2] + b0),
                                        rnd_tf32(acc[mt][nt][3] + b1));
                const int sel = col >> 10;
                const int h   = (col & 1023) >> 6;
                const int d0  = col & 63;
                float* dst = (sel == 0) ? g_Q : (sel == 1) ? g_K : g_V;
                const int bb = row >> 11;
                const int t  = row & (NT - 1);
                float* p = dst + (((size_t)(bb * NH + h) * NT + t) * ND + d0);
                *(float2*)p = v0;
                *(float2*)(p + 8*ND) = v1;
            } else {
                float2 v0 = make_float2(acc[mt][nt][0] + b0, acc[mt][nt][1] + b1);
                float2 v1 = make_float2(acc[mt][nt][2] + b0, acc[mt][nt][3] + b1);
                float* p = Cout + (size_t)row * NC + col;
                *(float2*)p = v0;
                *(float2*)(p + 8*NC) = v1;
            }
        }
    }
}

// ===========================================================================
// Flash attention, mma.sync tf32, q-tile 128 (8 warps x 16 rows, 256 thr).
// Q/K/V pre-rounded to tf32 by gemm<0> epilogue -> raw LDS feeds MMA.
// K/V tiles 64 rows, double-buffered cp.async. Softmax in log2 domain.
// P rounded at store-side; AO epilogue rounded for gemm<1>.
// ===========================================================================
#define SKV_K 68
#define SKV_V 72
#define A_KOFF 0
#define A_KSZ (64*SKV_K)                  // 4352 floats
#define A_VOFF (2*A_KSZ)                  // 8704
#define A_VSZ (64*SKV_V)                  // 4608
#define A_QPOFF (A_VOFF + 2*A_VSZ)        // 17920
#define A_QPSZ (128*SKV_K)                // 8704 floats
#define ATTN_SMEM ((A_QPOFF + A_QPSZ)*4)  // 106496 B

__device__ __forceinline__ void attn_load_kv(const float* Kt, const float* Vt,
                                             unsigned kb, unsigned vb, int tid)
{
    #pragma unroll
    for (int i = 0; i < 4; i++) {         // K: 64 rows x 16 f4 = 1024 f4
        int idx = tid + 256*i;
        int row = idx >> 4, c4 = idx & 15;
        cp_async16(kb + row*(SKV_K*4) + c4*16, Kt + (size_t)row*ND + c4*4);
    }
    #pragma unroll
    for (int i = 0; i < 4; i++) {
        int idx = tid + 256*i;
        int row = idx >> 4, c4 = idx & 15;
        cp_async16(vb + row*(SKV_V*4) + c4*16, Vt + (size_t)row*ND + c4*4);
    }
}

__global__ __launch_bounds__(256) void attn_mma()
{
    extern __shared__ float sm[];
    const unsigned sb = smem_u32(sm);
    const int tid = threadIdx.x, wid = tid >> 5, lane = tid & 31;
    const int lr = lane >> 2, lc = lane & 3;
    const int qt = (int)gridDim.x - 1 - (int)blockIdx.x;   // heavy tiles first
    const int bh = blockIdx.y;
    const int q0 = qt * 128;
    const int nkt = 2*qt + 2;

    const float* Qp = g_Q + (size_t)bh * NT * ND;
    const float* Kp = g_K + (size_t)bh * NT * ND;
    const float* Vp = g_V + (size_t)bh * NT * ND;

    // Q tile (128x64) -> QP region (stride 68); K/V tile 0 -> stage 0
    #pragma unroll
    for (int i = 0; i < 8; i++) {         // 128 rows x 16 f4 = 2048 f4
        int idx = tid + 256*i;
        int row = idx >> 4, c4 = idx & 15;
        cp_async16(sb + (A_QPOFF + row*SKV_K)*4 + c4*16,
                   Qp + (size_t)(q0 + row)*ND + c4*4);
    }
    attn_load_kv(Kp, Vp, sb + A_KOFF*4, sb + A_VOFF*4, tid);
    CP_COMMIT();
    CP_WAIT(0);
    __syncthreads();

    // Q fragments, pre-scaled by 1/8 * log2(e); re-round after scaling
    const float qsc = 0.125f * 1.44269504f;
    unsigned qa[8][4];
    {
        const float* Pq = sm + A_QPOFF + (wid*16)*SKV_K;
        #pragma unroll
        for (int k0 = 0; k0 < 8; k0++) {
            qa[k0][0] = f2tf32(Pq[(lr  )*SKV_K + k0*8 + lc    ] * qsc);
            qa[k0][1] = f2tf32(Pq[(lr+8)*SKV_K + k0*8 + lc    ] * qsc);
            qa[k0][2] = f2tf32(Pq[(lr  )*SKV_K + k0*8 + lc + 4] * qsc);
            qa[k0][3] = f2tf32(Pq[(lr+8)*SKV_K + k0*8 + lc + 4] * qsc);
        }
    }
    __syncwarp();      // all Q reads in this warp's slab done before P overwrites

    float m0 = -1e30f, m1 = -1e30f, l0 = 0.f, l1 = 0.f;
    float o[8][4];
    #pragma unroll
    for (int nt = 0; nt < 8; nt++) { o[nt][0]=o[nt][1]=o[nt][2]=o[nt][3]=0.f; }

    float* Pw = sm + A_QPOFF + (wid*16)*SKV_K;

    for (int kt = 0; kt < nkt; kt++) {
        const int st = kt & 1;
        CP_WAIT(0);
        __syncthreads();
        if (kt + 1 < nkt) {
            attn_load_kv(Kp + (size_t)(kt+1)*64*ND, Vp + (size_t)(kt+1)*64*ND,
                         sb + (A_KOFF + (st^1)*A_KSZ)*4,
                         sb + (A_VOFF + (st^1)*A_VSZ)*4, tid);
            CP_COMMIT();
        }

        const unsigned* Ks = (const unsigned*)(sm + A_KOFF + st*A_KSZ);
        const float*    Vs = sm + A_VOFF + st*A_VSZ;

        // S = Q * K^T   (per warp: 16 x 64)
        float s[8][4];
        #pragma unroll
        for (int nt = 0; nt < 8; nt++) { s[nt][0]=s[nt][1]=s[nt][2]=s[nt][3]=0.f; }
        #pragma unroll
        for (int nt = 0; nt < 8; nt++) {
            #pragma unroll
            for (int k0 = 0; k0 < 8; k0++) {
                unsigned b[2];
                b[0] = Ks[(nt*8 + lr)*SKV_K + k0*8 + lc    ];
                b[1] = Ks[(nt*8 + lr)*SKV_K + k0*8 + lc + 4];
                mma_tf32(s[nt], qa[k0], b);
            }
        }

        // causal mask for the diagonal band (last two k-tiles)
        if (kt >= 2*qt) {
            const int r0g = q0 + wid*16 + lr;
            #pragma unroll
            for (int nt = 0; nt < 8; nt++) {
                const int c0 = kt*64 + nt*8 + 2*lc;
                if (c0     > r0g    ) s[nt][0] = -1e30f;
                if (c0 + 1 > r0g    ) s[nt][1] = -1e30f;
                if (c0     > r0g + 8) s[nt][2] = -1e30f;
                if (c0 + 1 > r0g + 8) s[nt][3] = -1e30f;
            }
        }

        // online softmax (log2 domain)
        float tm0 = -1e30f, tm1 = -1e30f;
        #pragma unroll
        for (int nt = 0; nt < 8; nt++) {
            tm0 = fmaxf(tm0, fmaxf(s[nt][0], s[nt][1]));
            tm1 = fmaxf(tm1, fmaxf(s[nt][2], s[nt][3]));
        }
        tm0 = fmaxf(tm0, __shfl_xor_sync(0xffffffffu, tm0, 1));
        tm0 = fmaxf(tm0, __shfl_xor_sync(0xffffffffu, tm0, 2));
        tm1 = fmaxf(tm1, __shfl_xor_sync(0xffffffffu, tm1, 1));
        tm1 = fmaxf(tm1, __shfl_xor_sync(0xffffffffu, tm1, 2));

        const float mn0 = fmaxf(m0, tm0), mn1 = fmaxf(m1, tm1);
        const float sc0 = ex2f(m0 - mn0), sc1 = ex2f(m1 - mn1);
        m0 = mn0; m1 = mn1;

        float rs0 = 0.f, rs1 = 0.f;
        #pragma unroll
        for (int nt = 0; nt < 8; nt++) {
            float p0 = ex2f(s[nt][0] - mn0);
            float p1 = ex2f(s[nt][1] - mn0);
            float p2 = ex2f(s[nt][2] - mn1);
            float p3 = ex2f(s[nt][3] - mn1);
            rs0 += p0 + p1;
            rs1 += p2 + p3;
            *(float2*)&Pw[(lr  )*SKV_K + nt*8 + 2*lc] =
                make_float2(rnd_tf32(p0), rnd_tf32(p1));
            *(float2*)&Pw[(lr+8)*SKV_K + nt*8 + 2*lc] =
                make_float2(rnd_tf32(p2), rnd_tf32(p3));
        }
        rs0 += __shfl_xor_sync(0xffffffffu, rs0, 1);
        rs0 += __shfl_xor_sync(0xffffffffu, rs0, 2);
        rs1 += __shfl_xor_sync(0xffffffffu, rs1, 1);
        rs1 += __shfl_xor_sync(0xffffffffu, rs1, 2);
        l0 = l0*sc0 + rs0;
        l1 = l1*sc1 + rs1;
        #pragma unroll
        for (int nt = 0; nt < 8; nt++) {
            o[nt][0] *= sc0; o[nt][1] *= sc0;
            o[nt][2] *= sc1; o[nt][3] *= sc1;
        }
        __syncwarp();

        // O += P * V
        const unsigned* Pu = (const unsigned*)Pw;
        #pragma unroll
        for (int k0 = 0; k0 < 8; k0++) {
            unsigned a[4];
            a[0] = Pu[(lr  )*SKV_K + k0*8 + lc    ];
            a[1] = Pu[(lr+8)*SKV_K + k0*8 + lc    ];
            a[2] = Pu[(lr  )*SKV_K + k0*8 + lc + 4];
            a[3] = Pu[(lr+8)*SKV_K + k0*8 + lc + 4];
            const unsigned* Vu = (const unsigned*)Vs;
            #pragma unroll
            for (int nt = 0; nt < 8; nt++) {
                unsigned b[2];
                b[0] = Vu[(k0*8 + lc    )*SKV_V + nt*8 + lr];
                b[1] = Vu[(k0*8 + lc + 4)*SKV_V + nt*8 + lr];
                mma_tf32(o[nt], a, b);
            }
        }
        __syncwarp();   // P slab reads done before next iteration's stores
    }

    // epilogue: normalize, round to tf32 (gemm<1> A-operand), scatter to g_AO
    const float inv0 = 1.f / l0, inv1 = 1.f / l1;
    const int b = bh >> 4, h = bh & 15;
    const int r0 = q0 + wid*16 + lr, r1 = r0 + 8;
    #pragma unroll
    for (int nt = 0; nt < 8; nt++) {
        const int col = nt*8 + 2*lc;
        *(float2*)&g_AO[((size_t)(b*NT + r0))*NC + h*ND + col] =
            make_float2(rnd_tf32(o[nt][0]*inv0), rnd_tf32(o[nt][1]*inv0));
        *(float2*)&g_AO[((size_t)(b*NT + r1))*NC + h*ND + col] =
            make_float2(rnd_tf32(o[nt][2]*inv1), rnd_tf32(o[nt][3]*inv1));
    }
}

// ---------------------------------------------------------------------------
extern "C" void kernel_launch(void* const* d_in, const int* in_sizes, int n_in,
                              void* d_out, int out_size)
{
    const float* x     = (const float*)d_in[0];
    const float* Wqkv  = (const float*)d_in[1];
    const float* bqkv  = (const float*)d_in[2];
    const float* Wout  = (const float*)d_in[3];
    const float* bout  = (const float*)d_in[4];
    float* out = (float*)d_out;

    static int cfg_done = 0;
    if (!cfg_done) {
        cudaFuncSetAttribute(gemm_mma<0>, cudaFuncAttributeMaxDynamicSharedMemorySize, GEMM_SMEM);
        cudaFuncSetAttribute(gemm_mma<1>, cudaFuncAttributeMaxDynamicSharedMemorySize, GEMM_SMEM);
        cudaFuncSetAttribute(attn_mma,    cudaFuncAttributeMaxDynamicSharedMemorySize, ATTN_SMEM);
        cfg_done = 1;
    }

    gemm_mma<0><<<dim3(N_QKV/BN, NM/BM), 256, GEMM_SMEM>>>(x, Wqkv, bqkv, nullptr);
    attn_mma<<<dim3(NT/128, NB*NH), 256, ATTN_SMEM>>>();
    gemm_mma<1><<<dim3(NC/BN, NM/BM), 256, GEMM_SMEM>>>(nullptr, Wout, bout, out);
}

// round 14
// speedup vs baseline: 10.1716x; 1.9107x over previous
#include <cuda_runtime.h>
#include <cuda_fp16.h>

#define NB 4
#define NT 2048
#define NC 1024
#define NH 16
#define ND 64
#define NM (NB*NT)      // 8192 rows
#define N_QKV (3*NC)    // 3072

// Scratch (device globals — no allocations allowed)
__device__ __half g_Qh[(size_t)NB*NH*NT*ND];   // [bh][t][d]
__device__ __half g_Kh[(size_t)NB*NH*NT*ND];   // [bh][t][d]
__device__ __half g_Vt[(size_t)NB*NH*ND*NT];   // [bh][d][t]  (transposed!)
__device__ __half g_AOh[(size_t)NM*NC];        // [b*t][C]
__device__ __half g_xh[(size_t)NM*NC];
__device__ __half g_Wqh[(size_t)N_QKV*NC];
__device__ __half g_Woh[(size_t)NC*NC];

__device__ __forceinline__ unsigned smem_u32(const void* p) {
    unsigned a;
    asm("{ .reg .u64 t; cvta.to.shared.u64 t, %1; cvt.u32.u64 %0, t; }"
        : "=r"(a) : "l"(p));
    return a;
}
__device__ __forceinline__ void cp_async16(unsigned dst, const void* src) {
    asm volatile("cp.async.cg.shared.global [%0], [%1], 16;" :: "r"(dst), "l"(src));
}
#define CP_COMMIT()  asm volatile("cp.async.commit_group;" ::: "memory")
#define CP_WAIT(n)   asm volatile("cp.async.wait_group %0;" :: "n"(n) : "memory")

__device__ __forceinline__ float ex2f(float x) {
    float y; asm("ex2.approx.f32 %0, %1;" : "=f"(y) : "f"(x)); return y;
}
__device__ __forceinline__ unsigned h2u(__half2 h) { return *(unsigned*)&h; }

// fp16 mma: D(f32) = A(f16) * B(f16) + C(f32), m16n8k16, A row-major, B col-major
__device__ __forceinline__ void mma_f16(float c[4], const unsigned a[4], const unsigned b[2]) {
    asm volatile(
        "mma.sync.aligned.m16n8k16.row.col.f32.f16.f16.f32 "
        "{%0,%1,%2,%3}, {%4,%5,%6,%7}, {%8,%9}, {%0,%1,%2,%3};"
        : "+f"(c[0]), "+f"(c[1]), "+f"(c[2]), "+f"(c[3])
        : "r"(a[0]), "r"(a[1]), "r"(a[2]), "r"(a[3]), "r"(b[0]), "r"(b[1]));
}

// ===========================================================================
// fp32 -> fp16 conversion pass (grid-stride, float4 -> 2x half2)
// ===========================================================================
__global__ __launch_bounds__(256) void cvt_h(const float4* __restrict__ in,
                                             uint2* __restrict__ out, int n4)
{
    int i = blockIdx.x * blockDim.x + threadIdx.x;
    const int stride = gridDim.x * blockDim.x;
    for (; i < n4; i += stride) {
        float4 v = in[i];
        __half2 h0 = __floats2half2_rn(v.x, v.y);
        __half2 h1 = __floats2half2_rn(v.z, v.w);
        out[i] = make_uint2(h2u(h0), h2u(h1));
    }
}

// ===========================================================================
// fp16 mma GEMM: C[m][n] = sum_k A[m][k]*W[n][k] + bias[n], K=1024 halves.
// CTA tile 128x128, K-slab 64 halves (128 B rows, padded to 144 B), 256 thr,
// 3-stage cp.async, prefetch distance 2, one __syncthreads per iteration.
// MODE 0: A=g_xh,  W=g_Wqh; epilogue scatters fp16 into g_Qh/g_Kh/g_Vt.
// MODE 1: A=g_AOh, W=g_Woh; fp32 store + bias into Cout.
// ===========================================================================
#define BM 128
#define BN 128
#define BKH 64                                // halves per slab
#define SR2 36                                // half2 per padded row (144 B)
#define STAGE_BYTES (2*128*SR2*4)             // 36864 B
#define NSLAB_H (NC/BKH)                      // 16
#define GEMM_SMEM (3*STAGE_BYTES)             // 110592 B

__device__ __forceinline__ void load_slab_h(const __half* __restrict__ A,
                                            const __half* __restrict__ W,
                                            int m0, int n0, int slab, int st,
                                            unsigned sb, int tid)
{
    const unsigned abase = sb + st * STAGE_BYTES;
    const unsigned bbase = abase + 128*SR2*4;
    const __half* ag = A + (size_t)m0 * NC + slab * BKH;
    const __half* wg = W + (size_t)n0 * NC + slab * BKH;
    #pragma unroll
    for (int i = 0; i < 4; i++) {             // 128 rows x 8 chunks of 16B
        int idx = tid + 256 * i;
        int row = idx >> 3, c16 = idx & 7;
        cp_async16(abase + row * 144 + c16 * 16, ag + (size_t)row * NC + c16 * 8);
    }
    #pragma unroll
    for (int i = 0; i < 4; i++) {
        int idx = tid + 256 * i;
        int row = idx >> 3, c16 = idx & 7;
        cp_async16(bbase + row * 144 + c16 * 16, wg + (size_t)row * NC + c16 * 8);
    }
    CP_COMMIT();
}

template<int MODE>
__global__ __launch_bounds__(256) void gemm_h(const float* __restrict__ bias,
                                              float* __restrict__ Cout)
{
    extern __shared__ char smem[];
    const unsigned sb = smem_u32(smem);
    const int tid  = threadIdx.x;
    const int wid  = tid >> 5, lane = tid & 31;
    const int wm   = wid >> 2;                // 0..1  (64 rows)
    const int wn   = wid & 3;                 // 0..3  (32 cols)
    const int m0   = blockIdx.y * BM;
    const int n0   = blockIdx.x * BN;
    const __half* A = (MODE == 0) ? g_xh  : g_AOh;
    const __half* W = (MODE == 0) ? g_Wqh : g_Woh;

    const int lr = lane >> 2;
    const int lc = lane & 3;

    float acc[4][4][4];
    #pragma unroll
    for (int mt = 0; mt < 4; mt++)
        #pragma unroll
        for (int nt = 0; nt < 4; nt++)
            #pragma unroll
            for (int i = 0; i < 4; i++) acc[mt][nt][i] = 0.f;

    load_slab_h(A, W, m0, n0, 0, 0, sb, tid);
    load_slab_h(A, W, m0, n0, 1, 1, sb, tid);

    for (int i = 0; i < NSLAB_H; i++) {
        const int st = i % 3;
        if (i < NSLAB_H - 1) CP_WAIT(1);
        else                 CP_WAIT(0);
        __syncthreads();

        if (i + 2 < NSLAB_H)
            load_slab_h(A, W, m0, n0, i + 2, (i + 2) % 3, sb, tid);

        const unsigned* As = (const unsigned*)(smem + st * STAGE_BYTES);
        const unsigned* Bs = As + 128*SR2;

        #pragma unroll
        for (int k0 = 0; k0 < 4; k0++) {      // 4 mmas of k=16 per slab
            unsigned a[4][4], b[4][2];
            #pragma unroll
            for (int mt = 0; mt < 4; mt++) {
                const unsigned* p = As + (wm*64 + mt*16 + lr) * SR2 + k0*8 + lc;
                a[mt][0] = p[0];
                a[mt][1] = p[8*SR2];
                a[mt][2] = p[4];
                a[mt][3] = p[8*SR2 + 4];
            }
            #pragma unroll
            for (int nt = 0; nt < 4; nt++) {
                const unsigned* p = Bs + (wn*32 + nt*8 + lr) * SR2 + k0*8 + lc;
                b[nt][0] = p[0];
                b[nt][1] = p[4];
            }
            #pragma unroll
            for (int mt = 0; mt < 4; mt++)
                #pragma unroll
                for (int nt = 0; nt < 4; nt++)
                    mma_f16(acc[mt][nt], a[mt], b[nt]);
        }
    }

    #pragma unroll
    for (int mt = 0; mt < 4; mt++) {
        const int row = m0 + wm*64 + mt*16 + lr;
        #pragma unroll
        for (int nt = 0; nt < 4; nt++) {
            const int col = n0 + wn*32 + nt*8 + 2*lc;
            const float b0 = bias[col], b1 = bias[col + 1];
            const float v00 = acc[mt][nt][0] + b0, v01 = acc[mt][nt][1] + b1;
            const float v10 = acc[mt][nt][2] + b0, v11 = acc[mt][nt][3] + b1;
            if (MODE == 0) {
                const int sel = col >> 10;
                const int h   = (col & 1023) >> 6;
                const int d0  = col & 63;
                const int bb  = row >> 11;
                const int t   = row & (NT - 1);
                const size_t bh = (size_t)(bb * NH + h);
                if (sel == 2) {
                    // V transposed: g_Vt[bh][d][t]
                    __half* p = g_Vt + (bh * ND + d0) * NT + t;
                    p[0]        = __float2half_rn(v00);
                    p[NT]       = __float2half_rn(v01);
                    p[8]        = __float2half_rn(v10);   // row+8 -> t+8
                    p[NT + 8]   = __float2half_rn(v11);
                } else {
                    __half* dst = (sel == 0) ? g_Qh : g_Kh;
                    __half* p = dst + (bh * NT + t) * ND + d0;
                    *(unsigned*)p            = h2u(__floats2half2_rn(v00, v01));
                    *(unsigned*)(p + 8*ND)   = h2u(__floats2half2_rn(v10, v11));
                }
            } else {
                float* p = Cout + (size_t)row * NC + col;
                *(float2*)p          = make_float2(v00, v01);
                *(float2*)(p + 8*NC) = make_float2(v10, v11);
            }
        }
    }
}

// ===========================================================================
// Flash attention, fp16 mma, q-tile 128 (8 warps x 16 rows, 256 threads).
// All operands fp16 (written by gemm<0>), V pre-transposed in gmem.
// K/V tiles 64 keys, double-buffered. Softmax log2 domain, fp32 accums.
// Uniform padded rows: 36 half2 (144 B) -> conflict-free fragment gathers.
// SMEM 55296 B -> 2 CTAs/SM.
// ===========================================================================
#define A2_K  0                     // 2 stages x 64 rows x 36 h2 = 4608 h2
#define A2_V  4608
#define A2_QP 9216                  // 128 rows x 36 h2 (Q tile, then P slabs)
#define ATTN_SMEM ((A2_QP + 128*SR2)*4)   // 55296 B

__device__ __forceinline__ void attn_load_kv(const __half* Kt, const __half* VtT,
                                             unsigned kb, unsigned vb, int tid)
{
    #pragma unroll
    for (int i = 0; i < 2; i++) {   // K: 64 rows x 8 x 16B
        int idx = tid + 256*i;
        int row = idx >> 3, c16 = idx & 7;
        cp_async16(kb + row*144 + c16*16, Kt + (size_t)row*ND + c16*8);
    }
    #pragma unroll
    for (int i = 0; i < 2; i++) {   // Vt: 64 d-rows x 8 x 16B (keys contiguous)
        int idx = tid + 256*i;
        int row = idx >> 3, c16 = idx & 7;
        cp_async16(vb + row*144 + c16*16, VtT + (size_t)row*NT + c16*8);
    }
}

__global__ __launch_bounds__(256) void attn_mma()
{
    extern __shared__ char smc[];
    unsigned* sm2 = (unsigned*)smc;
    const unsigned sb = smem_u32(smc);
    const int tid = threadIdx.x, wid = tid >> 5, lane = tid & 31;
    const int lr = lane >> 2, lc = lane & 3;
    const int qt = (int)gridDim.x - 1 - (int)blockIdx.x;   // heavy tiles first
    const int bh = blockIdx.y;
    const int q0 = qt * 128;
    const int nkt = 2*qt + 2;

    const __half* Qp  = g_Qh + (size_t)bh * NT * ND;
    const __half* Kp  = g_Kh + (size_t)bh * NT * ND;
    const __half* VtT = g_Vt + (size_t)bh * ND * NT;

    // Q tile (128 x 64 halves) -> QP region; K/V tile 0 -> stage 0
    #pragma unroll
    for (int i = 0; i < 4; i++) {
        int idx = tid + 256*i;
        int row = idx >> 3, c16 = idx & 7;
        cp_async16(sb + (A2_QP + row*SR2)*4 + c16*16,
                   Qp + (size_t)(q0 + row)*ND + c16*8);
    }
    attn_load_kv(Kp, VtT, sb + A2_K*4, sb + A2_V*4, tid);
    CP_COMMIT();
    CP_WAIT(0);
    __syncthreads();

    // Q fragments: unpack, scale by 1/8*log2e, repack
    const float qsc = 0.125f * 1.44269504f;
    unsigned qa[4][4];
    {
        const unsigned* Q2 = sm2 + A2_QP + (wid*16)*SR2;
        #pragma unroll
        for (int k0 = 0; k0 < 4; k0++) {
            unsigned raw[4];
            raw[0] = Q2[(lr  )*SR2 + k0*8 + lc];
            raw[1] = Q2[(lr+8)*SR2 + k0*8 + lc];
            raw[2] = Q2[(lr  )*SR2 + k0*8 + lc + 4];
            raw[3] = Q2[(lr+8)*SR2 + k0*8 + lc + 4];
            #pragma unroll
            for (int j = 0; j < 4; j++) {
                float2 f = __half22float2(*(__half2*)&raw[j]);
                qa[k0][j] = h2u(__floats2half2_rn(f.x * qsc, f.y * qsc));
            }
        }
    }
    __syncwarp();   // Q slab reads done before P overwrites it

    float m0 = -1e30f, m1 = -1e30f, l0 = 0.f, l1 = 0.f;
    float o[8][4];
    #pragma unroll
    for (int nt = 0; nt < 8; nt++) { o[nt][0]=o[nt][1]=o[nt][2]=o[nt][3]=0.f; }

    unsigned* Pw = sm2 + A2_QP + (wid*16)*SR2;

    for (int kt = 0; kt < nkt; kt++) {
        const int st = kt & 1;
        CP_WAIT(0);
        __syncthreads();
        if (kt + 1 < nkt) {
            attn_load_kv(Kp + (size_t)(kt+1)*64*ND, VtT + (kt+1)*64,
                         sb + (A2_K + (st^1)*64*SR2)*4,
                         sb + (A2_V + (st^1)*64*SR2)*4, tid);
            CP_COMMIT();
        }

        const unsigned* Ks = sm2 + A2_K + st*64*SR2;
        const unsigned* Vs = sm2 + A2_V + st*64*SR2;

        // S = Q * K^T   (per warp: 16 x 64, k-dim = d = 64)
        float s[8][4];
        #pragma unroll
        for (int nt = 0; nt < 8; nt++) { s[nt][0]=s[nt][1]=s[nt][2]=s[nt][3]=0.f; }
        #pragma unroll
        for (int nt = 0; nt < 8; nt++) {
            #pragma unroll
            for (int k0 = 0; k0 < 4; k0++) {
                unsigned b[2];
                b[0] = Ks[(nt*8 + lr)*SR2 + k0*8 + lc];
                b[1] = Ks[(nt*8 + lr)*SR2 + k0*8 + lc + 4];
                mma_f16(s[nt], qa[k0], b);
            }
        }

        // causal mask for the diagonal band (last two k-tiles)
        if (kt >= 2*qt) {
            const int r0g = q0 + wid*16 + lr;
            #pragma unroll
            for (int nt = 0; nt < 8; nt++) {
                const int c0 = kt*64 + nt*8 + 2*lc;
                if (c0     > r0g    ) s[nt][0] = -1e30f;
                if (c0 + 1 > r0g    ) s[nt][1] = -1e30f;
                if (c0     > r0g + 8) s[nt][2] = -1e30f;
                if (c0 + 1 > r0g + 8) s[nt][3] = -1e30f;
            }
        }

        // online softmax (log2 domain)
        float tm0 = -1e30f, tm1 = -1e30f;
        #pragma unroll
        for (int nt = 0; nt < 8; nt++) {
            tm0 = fmaxf(tm0, fmaxf(s[nt][0], s[nt][1]));
            tm1 = fmaxf(tm1, fmaxf(s[nt][2], s[nt][3]));
        }
        tm0 = fmaxf(tm0, __shfl_xor_sync(0xffffffffu, tm0, 1));
        tm0 = fmaxf(tm0, __shfl_xor_sync(0xffffffffu, tm0, 2));
        tm1 = fmaxf(tm1, __shfl_xor_sync(0xffffffffu, tm1, 1));
        tm1 = fmaxf(tm1, __shfl_xor_sync(0xffffffffu, tm1, 2));

        const float mn0 = fmaxf(m0, tm0), mn1 = fmaxf(m1, tm1);
        const float sc0 = ex2f(m0 - mn0), sc1 = ex2f(m1 - mn1);
        m0 = mn0; m1 = mn1;

        float rs0 = 0.f, rs1 = 0.f;
        #pragma unroll
        for (int nt = 0; nt < 8; nt++) {
            float p0 = ex2f(s[nt][0] - mn0);
            float p1 = ex2f(s[nt][1] - mn0);
            float p2 = ex2f(s[nt][2] - mn1);
            float p3 = ex2f(s[nt][3] - mn1);
            rs0 += p0 + p1;
            rs1 += p2 + p3;
            Pw[(lr  )*SR2 + nt*4 + lc] = h2u(__floats2half2_rn(p0, p1));
            Pw[(lr+8)*SR2 + nt*4 + lc] = h2u(__floats2half2_rn(p2, p3));
        }
        rs0 += __shfl_xor_sync(0xffffffffu, rs0, 1);
        rs0 += __shfl_xor_sync(0xffffffffu, rs0, 2);
        rs1 += __shfl_xor_sync(0xffffffffu, rs1, 1);
        rs1 += __shfl_xor_sync(0xffffffffu, rs1, 2);
        l0 = l0*sc0 + rs0;
        l1 = l1*sc1 + rs1;
        #pragma unroll
        for (int nt = 0; nt < 8; nt++) {
            o[nt][0] *= sc0; o[nt][1] *= sc0;
            o[nt][2] *= sc1; o[nt][3] *= sc1;
        }
        __syncwarp();

        // O += P * V   (k-dim = 64 keys; B fragments from transposed V)
        #pragma unroll
        for (int k0 = 0; k0 < 4; k0++) {
            unsigned a[4];
            a[0] = Pw[(lr  )*SR2 + k0*8 + lc];
            a[1] = Pw[(lr+8)*SR2 + k0*8 + lc];
            a[2] = Pw[(lr  )*SR2 + k0*8 + lc + 4];
            a[3] = Pw[(lr+8)*SR2 + k0*8 + lc + 4];
            #pragma unroll
            for (int nt = 0; nt < 8; nt++) {
                unsigned b[2];
                b[0] = Vs[(nt*8 + lr)*SR2 + k0*8 + lc];
                b[1] = Vs[(nt*8 + lr)*SR2 + k0*8 + lc + 4];
                mma_f16(o[nt], a, b);
            }
        }
        __syncwarp();   // P reads done before next iteration overwrites
    }

    // epilogue: normalize, store fp16 AO for gemm<1>
    const float inv0 = 1.f / l0, inv1 = 1.f / l1;
    const int b = bh >> 4, h = bh & 15;
    const int r0 = q0 + wid*16 + lr, r1 = r0 + 8;
    unsigned* ao0 = (unsigned*)(g_AOh + ((size_t)(b*NT + r0))*NC + h*ND);
    unsigned* ao1 = (unsigned*)(g_AOh + ((size_t)(b*NT + r1))*NC + h*ND);
    #pragma unroll
    for (int nt = 0; nt < 8; nt++) {
        ao0[nt*4 + lc] = h2u(__floats2half2_rn(o[nt][0]*inv0, o[nt][1]*inv0));
        ao1[nt*4 + lc] = h2u(__floats2half2_rn(o[nt][2]*inv1, o[nt][3]*inv1));
    }
}

// ---------------------------------------------------------------------------
extern "C" void kernel_launch(void* const* d_in, const int* in_sizes, int n_in,
                              void* d_out, int out_size)
{
    const float* x     = (const float*)d_in[0];
    const float* Wqkv  = (const float*)d_in[1];
    const float* bqkv  = (const float*)d_in[2];
    const float* Wout  = (const float*)d_in[3];
    const float* bout  = (const float*)d_in[4];
    float* out = (float*)d_out;

    static int cfg_done = 0;
    if (!cfg_done) {
        cudaFuncSetAttribute(gemm_h<0>, cudaFuncAttributeMaxDynamicSharedMemorySize, GEMM_SMEM);
        cudaFuncSetAttribute(gemm_h<1>, cudaFuncAttributeMaxDynamicSharedMemorySize, GEMM_SMEM);
        cudaFuncSetAttribute(attn_mma,  cudaFuncAttributeMaxDynamicSharedMemorySize, ATTN_SMEM);
        cfg_done = 1;
    }

    // Device addresses of fp16 scratch (cudaGetSymbolAddress, NOT host shadow)
    void *xh, *wqh, *woh;
    cudaGetSymbolAddress(&xh,  g_xh);
    cudaGetSymbolAddress(&wqh, g_Wqh);
    cudaGetSymbolAddress(&woh, g_Woh);

    cvt_h<<<1184, 256>>>((const float4*)x,    (uint2*)xh,  NM*NC/4);
    cvt_h<<<1184, 256>>>((const float4*)Wqkv, (uint2*)wqh, N_QKV*NC/4);
    cvt_h<<<296,  256>>>((const float4*)Wout, (uint2*)woh, NC*NC/4);

    gemm_h<0><<<dim3(N_QKV/BN, NM/BM), 256, GEMM_SMEM>>>(bqkv, nullptr);
    attn_mma<<<dim3(NT/128, NB*NH), 256, ATTN_SMEM>>>();
    gemm_h<1><<<dim3(NC/BN, NM/BM), 256, GEMM_SMEM>>>(bout, out);
}

// round 15
// speedup vs baseline: 10.9508x; 1.0766x over previous
#include <cuda_runtime.h>
#include <cuda_fp16.h>

#define NB 4
#define NT 2048
#define NC 1024
#define NH 16
#define ND 64
#define NM (NB*NT)      // 8192 rows
#define N_QKV (3*NC)    // 3072

// Scratch (device globals — no allocations allowed)
__device__ __half g_Qh[(size_t)NB*NH*NT*ND];   // [bh][t][d]
__device__ __half g_Kh[(size_t)NB*NH*NT*ND];   // [bh][t][d]
__device__ __half g_Vt[(size_t)NB*NH*ND*NT];   // [bh][d][t]  (transposed)
__device__ __half g_AOh[(size_t)NM*NC];        // [b*t][C]
__device__ __half g_xh[(size_t)NM*NC];
__device__ __half g_Wqh[(size_t)N_QKV*NC];
__device__ __half g_Woh[(size_t)NC*NC];

__device__ __forceinline__ unsigned smem_u32(const void* p) {
    unsigned a;
    asm("{ .reg .u64 t; cvta.to.shared.u64 t, %1; cvt.u32.u64 %0, t; }"
        : "=r"(a) : "l"(p));
    return a;
}
__device__ __forceinline__ void cp_async16(unsigned dst, const void* src) {
    asm volatile("cp.async.cg.shared.global [%0], [%1], 16;" :: "r"(dst), "l"(src));
}
#define CP_COMMIT()  asm volatile("cp.async.commit_group;" ::: "memory")
#define CP_WAIT(n)   asm volatile("cp.async.wait_group %0;" :: "n"(n) : "memory")

#define LDSM4(r0,r1,r2,r3,a) \
    asm volatile("ldmatrix.sync.aligned.m8n8.x4.shared.b16 {%0,%1,%2,%3}, [%4];" \
        : "=r"(r0),"=r"(r1),"=r"(r2),"=r"(r3) : "r"(a))

__device__ __forceinline__ float ex2f(float x) {
    float y; asm("ex2.approx.f32 %0, %1;" : "=f"(y) : "f"(x)); return y;
}
__device__ __forceinline__ unsigned h2u(__half2 h) { return *(unsigned*)&h; }

__device__ __forceinline__ void mma_f16(float c[4], const unsigned a[4], const unsigned b[2]) {
    asm volatile(
        "mma.sync.aligned.m16n8k16.row.col.f32.f16.f16.f32 "
        "{%0,%1,%2,%3}, {%4,%5,%6,%7}, {%8,%9}, {%0,%1,%2,%3};"
        : "+f"(c[0]), "+f"(c[1]), "+f"(c[2]), "+f"(c[3])
        : "r"(a[0]), "r"(a[1]), "r"(a[2]), "r"(a[3]), "r"(b[0]), "r"(b[1]));
}

// ===========================================================================
// fp32 -> fp16 conversion pass
// ===========================================================================
__global__ __launch_bounds__(256) void cvt_h(const float4* __restrict__ in,
                                             uint2* __restrict__ out, int n4)
{
    int i = blockIdx.x * blockDim.x + threadIdx.x;
    const int stride = gridDim.x * blockDim.x;
    for (; i < n4; i += stride) {
        float4 v = in[i];
        out[i] = make_uint2(h2u(__floats2half2_rn(v.x, v.y)),
                            h2u(__floats2half2_rn(v.z, v.w)));
    }
}

// ===========================================================================
// fp16 ldmatrix GEMM: C[m][n] = sum_k A[m][k]*W[n][k] + bias[n], K=1024.
// CTA 128x128, K-slab 64 halves = 128B rows, XOR swizzle (chunk ^= row&7).
// 256 threads (8 warps 2x4), 3-stage cp.async, 1 barrier/iter.
// MODE 0: A=g_xh,  W=g_Wqh; scatter fp16 into g_Qh/g_Kh/g_Vt.
// MODE 1: A=g_AOh, W=g_Woh; fp32 store + bias.
// ===========================================================================
#define BM 128
#define BN 128
#define STAGE_BYTES (2*128*128)               // 32768 B
#define NSLAB_H (NC/64)                       // 16
#define GEMM_SMEM (3*STAGE_BYTES)             // 98304 B

__device__ __forceinline__ void load_slab_h(const __half* __restrict__ A,
                                            const __half* __restrict__ W,
                                            int m0, int n0, int slab, int st,
                                            unsigned sb, int tid)
{
    const unsigned abase = sb + st * STAGE_BYTES;
    const unsigned bbase = abase + 128*128;
    const __half* ag = A + (size_t)m0 * NC + slab * 64;
    const __half* wg = W + (size_t)n0 * NC + slab * 64;
    #pragma unroll
    for (int i = 0; i < 4; i++) {             // 128 rows x 8 chunks of 16B
        int idx = tid + 256 * i;
        int row = idx >> 3, c16 = idx & 7;
        unsigned sw = (unsigned)((c16 ^ (row & 7)) * 16);
        cp_async16(abase + row * 128 + sw, ag + (size_t)row * NC + c16 * 8);
    }
    #pragma unroll
    for (int i = 0; i < 4; i++) {
        int idx = tid + 256 * i;
        int row = idx >> 3, c16 = idx & 7;
        unsigned sw = (unsigned)((c16 ^ (row & 7)) * 16);
        cp_async16(bbase + row * 128 + sw, wg + (size_t)row * NC + c16 * 8);
    }
    CP_COMMIT();
}

template<int MODE>
__global__ __launch_bounds__(256) void gemm_h(const float* __restrict__ bias,
                                              float* __restrict__ Cout)
{
    extern __shared__ char smem[];
    const unsigned sb = smem_u32(smem);
    const int tid  = threadIdx.x;
    const int wid  = tid >> 5, lane = tid & 31;
    const int wm   = wid >> 2;                // 0..1
    const int wn   = wid & 3;                 // 0..3
    const int m0   = blockIdx.y * BM;
    const int n0   = blockIdx.x * BN;
    const __half* A = (MODE == 0) ? g_xh  : g_AOh;
    const __half* W = (MODE == 0) ? g_Wqh : g_Woh;

    const int lr = lane >> 2;
    const int lc = lane & 3;
    const int rsel = lane & 15;               // A-type row select
    const int csel = lane >> 4;               // chunk/tile select
    const int bsel = (lane >> 3) & 1;         // B-frag chunk select
    const unsigned swb = (unsigned)((lane & 7) * 16);

    // per-lane LDSM base offsets (within a stage)
    unsigned aBase[4], bBase[2];
    #pragma unroll
    for (int mt = 0; mt < 4; mt++)
        aBase[mt] = (unsigned)((wm*64 + mt*16 + rsel) * 128);
    #pragma unroll
    for (int p = 0; p < 2; p++)
        bBase[p] = (unsigned)(128*128 + (wn*32 + (2*p + csel)*8 + (lane & 7)) * 128);

    float acc[4][4][4];
    #pragma unroll
    for (int mt = 0; mt < 4; mt++)
        #pragma unroll
        for (int nt = 0; nt < 4; nt++)
            #pragma unroll
            for (int i = 0; i < 4; i++) acc[mt][nt][i] = 0.f;

    load_slab_h(A, W, m0, n0, 0, 0, sb, tid);
    load_slab_h(A, W, m0, n0, 1, 1, sb, tid);

    for (int i = 0; i < NSLAB_H; i++) {
        const int st = i % 3;
        if (i < NSLAB_H - 1) CP_WAIT(1);
        else                 CP_WAIT(0);
        __syncthreads();

        if (i + 2 < NSLAB_H)
            load_slab_h(A, W, m0, n0, i + 2, (i + 2) % 3, sb, tid);

        const unsigned stg = sb + st * STAGE_BYTES;

        #pragma unroll
        for (int k0 = 0; k0 < 4; k0++) {
            const unsigned offA = ((unsigned)(32*k0 + 16*csel)) ^ swb;
            const unsigned offB = ((unsigned)(32*k0 + 16*bsel)) ^ swb;
            unsigned a[4][4], b[4][2];
            #pragma unroll
            for (int mt = 0; mt < 4; mt++)
                LDSM4(a[mt][0], a[mt][1], a[mt][2], a[mt][3],
                      stg + aBase[mt] + offA);
            LDSM4(b[0][0], b[0][1], b[1][0], b[1][1], stg + bBase[0] + offB);
            LDSM4(b[2][0], b[2][1], b[3][0], b[3][1], stg + bBase[1] + offB);
            #pragma unroll
            for (int mt = 0; mt < 4; mt++)
                #pragma unroll
                for (int nt = 0; nt < 4; nt++)
                    mma_f16(acc[mt][nt], a[mt], b[nt]);
        }
    }

    #pragma unroll
    for (int mt = 0; mt < 4; mt++) {
        const int row = m0 + wm*64 + mt*16 + lr;
        #pragma unroll
        for (int nt = 0; nt < 4; nt++) {
            const int col = n0 + wn*32 + nt*8 + 2*lc;
            const float b0 = bias[col], b1 = bias[col + 1];
            const float v00 = acc[mt][nt][0] + b0, v01 = acc[mt][nt][1] + b1;
            const float v10 = acc[mt][nt][2] + b0, v11 = acc[mt][nt][3] + b1;
            if (MODE == 0) {
                const int sel = col >> 10;
                const int h   = (col & 1023) >> 6;
                const int d0  = col & 63;
                const int bb  = row >> 11;
                const int t   = row & (NT - 1);
                const size_t bh = (size_t)(bb * NH + h);
                if (sel == 2) {
                    __half* p = g_Vt + (bh * ND + d0) * NT + t;
                    p[0]      = __float2half_rn(v00);
                    p[NT]     = __float2half_rn(v01);
                    p[8]      = __float2half_rn(v10);
                    p[NT + 8] = __float2half_rn(v11);
                } else {
                    __half* dst = (sel == 0) ? g_Qh : g_Kh;
                    __half* p = dst + (bh * NT + t) * ND + d0;
                    *(unsigned*)p          = h2u(__floats2half2_rn(v00, v01));
                    *(unsigned*)(p + 8*ND) = h2u(__floats2half2_rn(v10, v11));
                }
            } else {
                float* p = Cout + (size_t)row * NC + col;
                *(float2*)p          = make_float2(v00, v01);
                *(float2*)(p + 8*NC) = make_float2(v10, v11);
            }
        }
    }
}

// ===========================================================================
// Flash attention, fp16 ldmatrix, q-tile 128 (8 warps x 16 rows, 256 thr).
// All tiles in XOR-swizzled 128B rows. K/V double-buffered.
// P written swizzled into the Q region (per-warp 16-row slab), read via LDSM.
// SMEM: K 16KB + V 16KB + QP 16KB = 48KB.
// ===========================================================================
#define AK_OFF 0                     // 2 stages x 8192 B
#define AV_OFF 16384                 // 2 stages x 8192 B
#define AQP_OFF 32768                // 128 rows x 128 B
#define ATTN_SMEM 49152

__device__ __forceinline__ void attn_load_kv(const __half* Kt, const __half* VtT,
                                             unsigned kb, unsigned vb, int tid)
{
    #pragma unroll
    for (int i = 0; i < 2; i++) {    // 64 rows x 8 chunks
        int idx = tid + 256*i;
        int row = idx >> 3, c16 = idx & 7;
        unsigned sw = (unsigned)((c16 ^ (row & 7)) * 16);
        cp_async16(kb + row*128 + sw, Kt + (size_t)row*ND + c16*8);
    }
    #pragma unroll
    for (int i = 0; i < 2; i++) {
        int idx = tid + 256*i;
        int row = idx >> 3, c16 = idx & 7;
        unsigned sw = (unsigned)((c16 ^ (row & 7)) * 16);
        cp_async16(vb + row*128 + sw, VtT + (size_t)row*NT + c16*8);
    }
}

__global__ __launch_bounds__(256) void attn_mma()
{
    extern __shared__ char smc[];
    const unsigned sb = smem_u32(smc);
    const int tid = threadIdx.x, wid = tid >> 5, lane = tid & 31;
    const int lr = lane >> 2, lc = lane & 3;
    const int rsel = lane & 15;
    const int csel = lane >> 4;
    const int bsel = (lane >> 3) & 1;
    const unsigned swb = (unsigned)((lane & 7) * 16);
    const int qt = (int)gridDim.x - 1 - (int)blockIdx.x;   // heavy tiles first
    const int bh = blockIdx.y;
    const int q0 = qt * 128;
    const int nkt = 2*qt + 2;

    const __half* Qp  = g_Qh + (size_t)bh * NT * ND;
    const __half* Kp  = g_Kh + (size_t)bh * NT * ND;
    const __half* VtT = g_Vt + (size_t)bh * ND * NT;

    // per-lane LDSM bases
    unsigned kvB[4];                 // b-frag rows within a 64-row K/V tile
    #pragma unroll
    for (int p = 0; p < 4; p++)
        kvB[p] = (unsigned)(((2*p + csel)*8 + (lane & 7)) * 128);
    const unsigned qpA = (unsigned)((wid*16 + rsel) * 128);   // a-frag rows

    // Q tile (128 x 64 halves) -> QP region (swizzled); K/V tile 0 -> stage 0
    #pragma unroll
    for (int i = 0; i < 4; i++) {
        int idx = tid + 256*i;
        int row = idx >> 3, c16 = idx & 7;
        unsigned sw = (unsigned)((c16 ^ (row & 7)) * 16);
        cp_async16(sb + AQP_OFF + row*128 + sw, Qp + (size_t)(q0 + row)*ND + c16*8);
    }
    attn_load_kv(Kp, VtT, sb + AK_OFF, sb + AV_OFF, tid);
    CP_COMMIT();
    CP_WAIT(0);
    __syncthreads();

    // Q fragments via LDSM: unpack, scale by 1/8*log2e, repack
    const float qsc = 0.125f * 1.44269504f;
    unsigned qa[4][4];
    #pragma unroll
    for (int k0 = 0; k0 < 4; k0++) {
        const unsigned offA = ((unsigned)(32*k0 + 16*csel)) ^ swb;
        unsigned raw[4];
        LDSM4(raw[0], raw[1], raw[2], raw[3], sb + AQP_OFF + qpA + offA);
        #pragma unroll
        for (int j = 0; j < 4; j++) {
            float2 f = __half22float2(*(__half2*)&raw[j]);
            qa[k0][j] = h2u(__floats2half2_rn(f.x * qsc, f.y * qsc));
        }
    }
    __syncwarp();   // Q slab reads done before P overwrites it

    float m0 = -1e30f, m1 = -1e30f, l0 = 0.f, l1 = 0.f;
    float o[8][4];
    #pragma unroll
    for (int nt = 0; nt < 8; nt++) { o[nt][0]=o[nt][1]=o[nt][2]=o[nt][3]=0.f; }

    // P store pointers (swizzled rows in the per-warp QP slab)
    char* Prow0 = smc + AQP_OFF + (wid*16 + lr    )*128 + 4*lc;
    char* Prow1 = smc + AQP_OFF + (wid*16 + lr + 8)*128 + 4*lc;
    const unsigned pxor = (unsigned)(lr * 16);   // (lr&7)*16, lr<8

    for (int kt = 0; kt < nkt; kt++) {
        const int st = kt & 1;
        CP_WAIT(0);
        __syncthreads();
        if (kt + 1 < nkt) {
            attn_load_kv(Kp + (size_t)(kt+1)*64*ND, VtT + (kt+1)*64,
                         sb + AK_OFF + (st^1)*8192,
                         sb + AV_OFF + (st^1)*8192, tid);
            CP_COMMIT();
        }

        const unsigned kstg = sb + AK_OFF + st*8192;
        const unsigned vstg = sb + AV_OFF + st*8192;

        // S = Q * K^T   (per warp: 16 x 64, k-dim = d = 64)
        float s[8][4];
        #pragma unroll
        for (int nt = 0; nt < 8; nt++) { s[nt][0]=s[nt][1]=s[nt][2]=s[nt][3]=0.f; }
        #pragma unroll
        for (int k0 = 0; k0 < 4; k0++) {
            const unsigned offB = ((unsigned)(32*k0 + 16*bsel)) ^ swb;
            #pragma unroll
            for (int p = 0; p < 4; p++) {
                unsigned b[4];
                LDSM4(b[0], b[1], b[2], b[3], kstg + kvB[p] + offB);
                mma_f16(s[2*p    ], qa[k0], b);
                mma_f16(s[2*p + 1], qa[k0], b + 2);
            }
        }

        // causal mask for the diagonal band (last two k-tiles)
        if (kt >= 2*qt) {
            const int r0g = q0 + wid*16 + lr;
            #pragma unroll
            for (int nt = 0; nt < 8; nt++) {
                const int c0 = kt*64 + nt*8 + 2*lc;
                if (c0     > r0g    ) s[nt][0] = -1e30f;
                if (c0 + 1 > r0g    ) s[nt][1] = -1e30f;
                if (c0     > r0g + 8) s[nt][2] = -1e30f;
                if (c0 + 1 > r0g + 8) s[nt][3] = -1e30f;
            }
        }

        // online softmax (log2 domain)
        float tm0 = -1e30f, tm1 = -1e30f;
        #pragma unroll
        for (int nt = 0; nt < 8; nt++) {
            tm0 = fmaxf(tm0, fmaxf(s[nt][0], s[nt][1]));
            tm1 = fmaxf(tm1, fmaxf(s[nt][2], s[nt][3]));
        }
        tm0 = fmaxf(tm0, __shfl_xor_sync(0xffffffffu, tm0, 1));
        tm0 = fmaxf(tm0, __shfl_xor_sync(0xffffffffu, tm0, 2));
        tm1 = fmaxf(tm1, __shfl_xor_sync(0xffffffffu, tm1, 1));
        tm1 = fmaxf(tm1, __shfl_xor_sync(0xffffffffu, tm1, 2));

        const float mn0 = fmaxf(m0, tm0), mn1 = fmaxf(m1, tm1);
        const float sc0 = ex2f(m0 - mn0), sc1 = ex2f(m1 - mn1);
        m0 = mn0; m1 = mn1;

        float rs0 = 0.f, rs1 = 0.f;
        #pragma unroll
        for (int nt = 0; nt < 8; nt++) {
            float p0 = ex2f(s[nt][0] - mn0);
            float p1 = ex2f(s[nt][1] - mn0);
            float p2 = ex2f(s[nt][2] - mn1);
            float p3 = ex2f(s[nt][3] - mn1);
            rs0 += p0 + p1;
            rs1 += p2 + p3;
            const unsigned cx = ((unsigned)(nt*16)) ^ pxor;   // chunk ^ row swizzle
            *(unsigned*)(Prow0 + cx) = h2u(__floats2half2_rn(p0, p1));
            *(unsigned*)(Prow1 + cx) = h2u(__floats2half2_rn(p2, p3));
        }
        rs0 += __shfl_xor_sync(0xffffffffu, rs0, 1);
        rs0 += __shfl_xor_sync(0xffffffffu, rs0, 2);
        rs1 += __shfl_xor_sync(0xffffffffu, rs1, 1);
        rs1 += __shfl_xor_sync(0xffffffffu, rs1, 2);
        l0 = l0*sc0 + rs0;
        l1 = l1*sc1 + rs1;
        #pragma unroll
        for (int nt = 0; nt < 8; nt++) {
            o[nt][0] *= sc0; o[nt][1] *= sc0;
            o[nt][2] *= sc1; o[nt][3] *= sc1;
        }
        __syncwarp();

        // O += P * V   (k-dim = 64 keys; a-frags = P via LDSM, b-frags = Vt)
        #pragma unroll
        for (int k0 = 0; k0 < 4; k0++) {
            const unsigned offA = ((unsigned)(32*k0 + 16*csel)) ^ swb;
            const unsigned offB = ((unsigned)(32*k0 + 16*bsel)) ^ swb;
            unsigned a[4];
            LDSM4(a[0], a[1], a[2], a[3], sb + AQP_OFF + qpA + offA);
            #pragma unroll
            for (int p = 0; p < 4; p++) {
                unsigned b[4];
                LDSM4(b[0], b[1], b[2], b[3], vstg + kvB[p] + offB);
                mma_f16(o[2*p    ], a, b);
                mma_f16(o[2*p + 1], a, b + 2);
            }
        }
        __syncwarp();   // P reads done before next iteration overwrites
    }

    // epilogue: normalize, store fp16 AO for gemm<1>
    const float inv0 = 1.f / l0, inv1 = 1.f / l1;
    const int b = bh >> 4, h = bh & 15;
    const int r0 = q0 + wid*16 + lr, r1 = r0 + 8;
    unsigned* ao0 = (unsigned*)(g_AOh + ((size_t)(b*NT + r0))*NC + h*ND);
    unsigned* ao1 = (unsigned*)(g_AOh + ((size_t)(b*NT + r1))*NC + h*ND);
    #pragma unroll
    for (int nt = 0; nt < 8; nt++) {
        ao0[nt*4 + lc] = h2u(__floats2half2_rn(o[nt][0]*inv0, o[nt][1]*inv0));
        ao1[nt*4 + lc] = h2u(__floats2half2_rn(o[nt][2]*inv1, o[nt][3]*inv1));
    }
}

// ---------------------------------------------------------------------------
extern "C" void kernel_launch(void* const* d_in, const int* in_sizes, int n_in,
                              void* d_out, int out_size)
{
    const float* x     = (const float*)d_in[0];
    const float* Wqkv  = (const float*)d_in[1];
    const float* bqkv  = (const float*)d_in[2];
    const float* Wout  = (const float*)d_in[3];
    const float* bout  = (const float*)d_in[4];
    float* out = (float*)d_out;

    static int cfg_done = 0;
    if (!cfg_done) {
        cudaFuncSetAttribute(gemm_h<0>, cudaFuncAttributeMaxDynamicSharedMemorySize, GEMM_SMEM);
        cudaFuncSetAttribute(gemm_h<1>, cudaFuncAttributeMaxDynamicSharedMemorySize, GEMM_SMEM);
        cudaFuncSetAttribute(attn_mma,  cudaFuncAttributeMaxDynamicSharedMemorySize, ATTN_SMEM);
        cfg_done = 1;
    }

    void *xh, *wqh, *woh;
    cudaGetSymbolAddress(&xh,  g_xh);
    cudaGetSymbolAddress(&wqh, g_Wqh);
    cudaGetSymbolAddress(&woh, g_Woh);

    cvt_h<<<1184, 256>>>((const float4*)x,    (uint2*)xh,  NM*NC/4);
    cvt_h<<<1184, 256>>>((const float4*)Wqkv, (uint2*)wqh, N_QKV*NC/4);
    cvt_h<<<296,  256>>>((const float4*)Wout, (uint2*)woh, NC*NC/4);

    gemm_h<0><<<dim3(N_QKV/BN, NM/BM), 256, GEMM_SMEM>>>(bqkv, nullptr);
    attn_mma<<<dim3(NT/128, NB*NH), 256, ATTN_SMEM>>>();
    gemm_h<1><<<dim3(NC/BN, NM/BM), 256, GEMM_SMEM>>>(bout, out);
}

// round 16
// speedup vs baseline: 12.2223x; 1.1161x over previous
#include <cuda_runtime.h>
#include <cuda_fp16.h>

#define NB 4
#define NT 2048
#define NC 1024
#define NH 16
#define ND 64
#define NM (NB*NT)      // 8192 rows
#define N_QKV (3*NC)    // 3072

// Scratch (device globals — no allocations allowed)
__device__ __half g_Qh[(size_t)NB*NH*NT*ND];   // [bh][t][d]
__device__ __half g_Kh[(size_t)NB*NH*NT*ND];   // [bh][t][d]
__device__ __half g_Vt[(size_t)NB*NH*ND*NT];   // [bh][d][t]  (transposed)
__device__ __half g_AOh[(size_t)NM*NC];        // [b*t][C]
__device__ __half g_xh[(size_t)NM*NC];
__device__ __half g_Wqh[(size_t)N_QKV*NC];
__device__ __half g_Woh[(size_t)NC*NC];

__device__ __forceinline__ unsigned smem_u32(const void* p) {
    unsigned a;
    asm("{ .reg .u64 t; cvta.to.shared.u64 t, %1; cvt.u32.u64 %0, t; }"
        : "=r"(a) : "l"(p));
    return a;
}
__device__ __forceinline__ void cp_async16(unsigned dst, const void* src) {
    asm volatile("cp.async.cg.shared.global [%0], [%1], 16;" :: "r"(dst), "l"(src));
}
#define CP_COMMIT()  asm volatile("cp.async.commit_group;" ::: "memory")
#define CP_WAIT(n)   asm volatile("cp.async.wait_group %0;" :: "n"(n) : "memory")

#define LDSM4(r0,r1,r2,r3,a) \
    asm volatile("ldmatrix.sync.aligned.m8n8.x4.shared.b16 {%0,%1,%2,%3}, [%4];" \
        : "=r"(r0),"=r"(r1),"=r"(r2),"=r"(r3) : "r"(a))

__device__ __forceinline__ float ex2f(float x) {
    float y; asm("ex2.approx.f32 %0, %1;" : "=f"(y) : "f"(x)); return y;
}
__device__ __forceinline__ unsigned h2u(__half2 h) { return *(unsigned*)&h; }

__device__ __forceinline__ void mma_f16(float c[4], const unsigned a[4], const unsigned b[2]) {
    asm volatile(
        "mma.sync.aligned.m16n8k16.row.col.f32.f16.f16.f32 "
        "{%0,%1,%2,%3}, {%4,%5,%6,%7}, {%8,%9}, {%0,%1,%2,%3};"
        : "+f"(c[0]), "+f"(c[1]), "+f"(c[2]), "+f"(c[3])
        : "r"(a[0]), "r"(a[1]), "r"(a[2]), "r"(a[3]), "r"(b[0]), "r"(b[1]));
}

// ===========================================================================
// fp32 -> fp16 conversion pass
// ===========================================================================
__global__ __launch_bounds__(256) void cvt_h(const float4* __restrict__ in,
                                             uint2* __restrict__ out, int n4)
{
    int i = blockIdx.x * blockDim.x + threadIdx.x;
    const int stride = gridDim.x * blockDim.x;
    for (; i < n4; i += stride) {
        float4 v = in[i];
        out[i] = make_uint2(h2u(__floats2half2_rn(v.x, v.y)),
                            h2u(__floats2half2_rn(v.z, v.w)));
    }
}

// ===========================================================================
// fp16 ldmatrix GEMM (unchanged from round 15): C = A*W^T + bias, K=1024.
// CTA 128x128, K-slab 64 halves = 128B rows, XOR swizzle (chunk ^= row&7).
// 256 threads (8 warps 2x4), 3-stage cp.async, 1 barrier/iter.
// MODE 0: A=g_xh,  W=g_Wqh; scatter fp16 into g_Qh/g_Kh/g_Vt.
// MODE 1: A=g_AOh, W=g_Woh; fp32 store + bias.
// ===========================================================================
#define BM 128
#define BN 128
#define STAGE_BYTES (2*128*128)               // 32768 B
#define NSLAB_H (NC/64)                       // 16
#define GEMM_SMEM (3*STAGE_BYTES)             // 98304 B

__device__ __forceinline__ void load_slab_h(const __half* __restrict__ A,
                                            const __half* __restrict__ W,
                                            int m0, int n0, int slab, int st,
                                            unsigned sb, int tid)
{
    const unsigned abase = sb + st * STAGE_BYTES;
    const unsigned bbase = abase + 128*128;
    const __half* ag = A + (size_t)m0 * NC + slab * 64;
    const __half* wg = W + (size_t)n0 * NC + slab * 64;
    #pragma unroll
    for (int i = 0; i < 4; i++) {             // 128 rows x 8 chunks of 16B
        int idx = tid + 256 * i;
        int row = idx >> 3, c16 = idx & 7;
        unsigned sw = (unsigned)((c16 ^ (row & 7)) * 16);
        cp_async16(abase + row * 128 + sw, ag + (size_t)row * NC + c16 * 8);
    }
    #pragma unroll
    for (int i = 0; i < 4; i++) {
        int idx = tid + 256 * i;
        int row = idx >> 3, c16 = idx & 7;
        unsigned sw = (unsigned)((c16 ^ (row & 7)) * 16);
        cp_async16(bbase + row * 128 + sw, wg + (size_t)row * NC + c16 * 8);
    }
    CP_COMMIT();
}

template<int MODE>
__global__ __launch_bounds__(256) void gemm_h(const float* __restrict__ bias,
                                              float* __restrict__ Cout)
{
    extern __shared__ char smem[];
    const unsigned sb = smem_u32(smem);
    const int tid  = threadIdx.x;
    const int wid  = tid >> 5, lane = tid & 31;
    const int wm   = wid >> 2;
    const int wn   = wid & 3;
    const int m0   = blockIdx.y * BM;
    const int n0   = blockIdx.x * BN;
    const __half* A = (MODE == 0) ? g_xh  : g_AOh;
    const __half* W = (MODE == 0) ? g_Wqh : g_Woh;

    const int lr = lane >> 2;
    const int lc = lane & 3;
    const int rsel = lane & 15;
    const int csel = lane >> 4;
    const int bsel = (lane >> 3) & 1;
    const unsigned swb = (unsigned)((lane & 7) * 16);

    unsigned aBase[4], bBase[2];
    #pragma unroll
    for (int mt = 0; mt < 4; mt++)
        aBase[mt] = (unsigned)((wm*64 + mt*16 + rsel) * 128);
    #pragma unroll
    for (int p = 0; p < 2; p++)
        bBase[p] = (unsigned)(128*128 + (wn*32 + (2*p + csel)*8 + (lane & 7)) * 128);

    float acc[4][4][4];
    #pragma unroll
    for (int mt = 0; mt < 4; mt++)
        #pragma unroll
        for (int nt = 0; nt < 4; nt++)
            #pragma unroll
            for (int i = 0; i < 4; i++) acc[mt][nt][i] = 0.f;

    load_slab_h(A, W, m0, n0, 0, 0, sb, tid);
    load_slab_h(A, W, m0, n0, 1, 1, sb, tid);

    for (int i = 0; i < NSLAB_H; i++) {
        const int st = i % 3;
        if (i < NSLAB_H - 1) CP_WAIT(1);
        else                 CP_WAIT(0);
        __syncthreads();

        if (i + 2 < NSLAB_H)
            load_slab_h(A, W, m0, n0, i + 2, (i + 2) % 3, sb, tid);

        const unsigned stg = sb + st * STAGE_BYTES;

        #pragma unroll
        for (int k0 = 0; k0 < 4; k0++) {
            const unsigned offA = ((unsigned)(32*k0 + 16*csel)) ^ swb;
            const unsigned offB = ((unsigned)(32*k0 + 16*bsel)) ^ swb;
            unsigned a[4][4], b[4][2];
            #pragma unroll
            for (int mt = 0; mt < 4; mt++)
                LDSM4(a[mt][0], a[mt][1], a[mt][2], a[mt][3],
                      stg + aBase[mt] + offA);
            LDSM4(b[0][0], b[0][1], b[1][0], b[1][1], stg + bBase[0] + offB);
            LDSM4(b[2][0], b[2][1], b[3][0], b[3][1], stg + bBase[1] + offB);
            #pragma unroll
            for (int mt = 0; mt < 4; mt++)
                #pragma unroll
                for (int nt = 0; nt < 4; nt++)
                    mma_f16(acc[mt][nt], a[mt], b[nt]);
        }
    }

    #pragma unroll
    for (int mt = 0; mt < 4; mt++) {
        const int row = m0 + wm*64 + mt*16 + lr;
        #pragma unroll
        for (int nt = 0; nt < 4; nt++) {
            const int col = n0 + wn*32 + nt*8 + 2*lc;
            const float b0 = bias[col], b1 = bias[col + 1];
            const float v00 = acc[mt][nt][0] + b0, v01 = acc[mt][nt][1] + b1;
            const float v10 = acc[mt][nt][2] + b0, v11 = acc[mt][nt][3] + b1;
            if (MODE == 0) {
                const int sel = col >> 10;
                const int h   = (col & 1023) >> 6;
                const int d0  = col & 63;
                const int bb  = row >> 11;
                const int t   = row & (NT - 1);
                const size_t bh = (size_t)(bb * NH + h);
                if (sel == 2) {
                    __half* p = g_Vt + (bh * ND + d0) * NT + t;
                    p[0]      = __float2half_rn(v00);
                    p[NT]     = __float2half_rn(v01);
                    p[8]      = __float2half_rn(v10);
                    p[NT + 8] = __float2half_rn(v11);
                } else {
                    __half* dst = (sel == 0) ? g_Qh : g_Kh;
                    __half* p = dst + (bh * NT + t) * ND + d0;
                    *(unsigned*)p          = h2u(__floats2half2_rn(v00, v01));
                    *(unsigned*)(p + 8*ND) = h2u(__floats2half2_rn(v10, v11));
                }
            } else {
                float* p = Cout + (size_t)row * NC + col;
                *(float2*)p          = make_float2(v00, v01);
                *(float2*)(p + 8*NC) = make_float2(v10, v11);
            }
        }
    }
}

// ===========================================================================
// Flash attention, fp16 ldmatrix, q-tile 128 (8 warps x 16 rows, 256 thr).
// P KEPT IN REGISTERS: the m16n8k16 S-accumulator layout IS the A-operand
// layout for the PV mma (rows {lr,lr+8}, cols {nt*8+2lc,+1}); pack p-values
// straight into pa[k0][0..3]. No P SMEM roundtrip, no extra syncwarps.
// K/V tiles 64 keys, double-buffered, XOR-swizzled 128B rows.
// ===========================================================================
#define AK_OFF 0                     // 2 stages x 8192 B
#define AV_OFF 16384                 // 2 stages x 8192 B
#define AQP_OFF 32768                // 128 rows x 128 B (Q staging only)
#define ATTN_SMEM 49152

__device__ __forceinline__ void attn_load_kv(const __half* Kt, const __half* VtT,
                                             unsigned kb, unsigned vb, int tid)
{
    #pragma unroll
    for (int i = 0; i < 2; i++) {    // 64 rows x 8 chunks
        int idx = tid + 256*i;
        int row = idx >> 3, c16 = idx & 7;
        unsigned sw = (unsigned)((c16 ^ (row & 7)) * 16);
        cp_async16(kb + row*128 + sw, Kt + (size_t)row*ND + c16*8);
    }
    #pragma unroll
    for (int i = 0; i < 2; i++) {
        int idx = tid + 256*i;
        int row = idx >> 3, c16 = idx & 7;
        unsigned sw = (unsigned)((c16 ^ (row & 7)) * 16);
        cp_async16(vb + row*128 + sw, VtT + (size_t)row*NT + c16*8);
    }
}

__global__ __launch_bounds__(256) void attn_mma()
{
    extern __shared__ char smc[];
    const unsigned sb = smem_u32(smc);
    const int tid = threadIdx.x, wid = tid >> 5, lane = tid & 31;
    const int lr = lane >> 2, lc = lane & 3;
    const int rsel = lane & 15;
    const int csel = lane >> 4;
    const int bsel = (lane >> 3) & 1;
    const unsigned swb = (unsigned)((lane & 7) * 16);
    const int qt = (int)gridDim.x - 1 - (int)blockIdx.x;   // heavy tiles first
    const int bh = blockIdx.y;
    const int q0 = qt * 128;
    const int nkt = 2*qt + 2;

    const __half* Qp  = g_Qh + (size_t)bh * NT * ND;
    const __half* Kp  = g_Kh + (size_t)bh * NT * ND;
    const __half* VtT = g_Vt + (size_t)bh * ND * NT;

    unsigned kvB[4];                 // b-frag rows within a 64-row K/V tile
    #pragma unroll
    for (int p = 0; p < 4; p++)
        kvB[p] = (unsigned)(((2*p + csel)*8 + (lane & 7)) * 128);
    const unsigned qpA = (unsigned)((wid*16 + rsel) * 128);

    // Q tile (128 x 64 halves) -> QP region (swizzled); K/V tile 0 -> stage 0
    #pragma unroll
    for (int i = 0; i < 4; i++) {
        int idx = tid + 256*i;
        int row = idx >> 3, c16 = idx & 7;
        unsigned sw = (unsigned)((c16 ^ (row & 7)) * 16);
        cp_async16(sb + AQP_OFF + row*128 + sw, Qp + (size_t)(q0 + row)*ND + c16*8);
    }
    attn_load_kv(Kp, VtT, sb + AK_OFF, sb + AV_OFF, tid);
    CP_COMMIT();
    CP_WAIT(0);
    __syncthreads();

    // Q fragments via LDSM: unpack, scale by 1/8*log2e, repack
    const float qsc = 0.125f * 1.44269504f;
    unsigned qa[4][4];
    #pragma unroll
    for (int k0 = 0; k0 < 4; k0++) {
        const unsigned offA = ((unsigned)(32*k0 + 16*csel)) ^ swb;
        unsigned raw[4];
        LDSM4(raw[0], raw[1], raw[2], raw[3], sb + AQP_OFF + qpA + offA);
        #pragma unroll
        for (int j = 0; j < 4; j++) {
            float2 f = __half22float2(*(__half2*)&raw[j]);
            qa[k0][j] = h2u(__floats2half2_rn(f.x * qsc, f.y * qsc));
        }
    }

    float m0 = -1e30f, m1 = -1e30f, l0 = 0.f, l1 = 0.f;
    float o[8][4];
    #pragma unroll
    for (int nt = 0; nt < 8; nt++) { o[nt][0]=o[nt][1]=o[nt][2]=o[nt][3]=0.f; }

    for (int kt = 0; kt < nkt; kt++) {
        const int st = kt & 1;
        CP_WAIT(0);
        __syncthreads();
        if (kt + 1 < nkt) {
            attn_load_kv(Kp + (size_t)(kt+1)*64*ND, VtT + (kt+1)*64,
                         sb + AK_OFF + (st^1)*8192,
                         sb + AV_OFF + (st^1)*8192, tid);
            CP_COMMIT();
        }

        const unsigned kstg = sb + AK_OFF + st*8192;
        const unsigned vstg = sb + AV_OFF + st*8192;

        // S = Q * K^T   (per warp: 16 x 64, k-dim = d = 64)
        float s[8][4];
        #pragma unroll
        for (int nt = 0; nt < 8; nt++) { s[nt][0]=s[nt][1]=s[nt][2]=s[nt][3]=0.f; }
        #pragma unroll
        for (int k0 = 0; k0 < 4; k0++) {
            const unsigned offB = ((unsigned)(32*k0 + 16*bsel)) ^ swb;
            #pragma unroll
            for (int p = 0; p < 4; p++) {
                unsigned b[4];
                LDSM4(b[0], b[1], b[2], b[3], kstg + kvB[p] + offB);
                mma_f16(s[2*p    ], qa[k0], b);
                mma_f16(s[2*p + 1], qa[k0], b + 2);
            }
        }

        // causal mask for the diagonal band (last two k-tiles)
        if (kt >= 2*qt) {
            const int r0g = q0 + wid*16 + lr;
            #pragma unroll
            for (int nt = 0; nt < 8; nt++) {
                const int c0 = kt*64 + nt*8 + 2*lc;
                if (c0     > r0g    ) s[nt][0] = -1e30f;
                if (c0 + 1 > r0g    ) s[nt][1] = -1e30f;
                if (c0     > r0g + 8) s[nt][2] = -1e30f;
                if (c0 + 1 > r0g + 8) s[nt][3] = -1e30f;
            }
        }

        // online softmax (log2 domain)
        float tm0 = -1e30f, tm1 = -1e30f;
        #pragma unroll
        for (int nt = 0; nt < 8; nt++) {
            tm0 = fmaxf(tm0, fmaxf(s[nt][0], s[nt][1]));
            tm1 = fmaxf(tm1, fmaxf(s[nt][2], s[nt][3]));
        }
        tm0 = fmaxf(tm0, __shfl_xor_sync(0xffffffffu, tm0, 1));
        tm0 = fmaxf(tm0, __shfl_xor_sync(0xffffffffu, tm0, 2));
        tm1 = fmaxf(tm1, __shfl_xor_sync(0xffffffffu, tm1, 1));
        tm1 = fmaxf(tm1, __shfl_xor_sync(0xffffffffu, tm1, 2));

        const float mn0 = fmaxf(m0, tm0), mn1 = fmaxf(m1, tm1);
        const float sc0 = ex2f(m0 - mn0), sc1 = ex2f(m1 - mn1);
        m0 = mn0; m1 = mn1;

        // p-values -> fp16 A-fragments in registers (no SMEM roundtrip)
        unsigned pa[4][4];
        float rs0 = 0.f, rs1 = 0.f;
        #pragma unroll
        for (int nt = 0; nt < 8; nt++) {
            float p0 = ex2f(s[nt][0] - mn0);
            float p1 = ex2f(s[nt][1] - mn0);
            float p2 = ex2f(s[nt][2] - mn1);
            float p3 = ex2f(s[nt][3] - mn1);
            rs0 += p0 + p1;
            rs1 += p2 + p3;
            const int k0 = nt >> 1;
            if ((nt & 1) == 0) {
                pa[k0][0] = h2u(__floats2half2_rn(p0, p1));   // (lr,   16k0+2lc)
                pa[k0][1] = h2u(__floats2half2_rn(p2, p3));   // (lr+8, 16k0+2lc)
            } else {
                pa[k0][2] = h2u(__floats2half2_rn(p0, p1));   // (lr,   16k0+8+2lc)
                pa[k0][3] = h2u(__floats2half2_rn(p2, p3));   // (lr+8, 16k0+8+2lc)
            }
        }
        rs0 += __shfl_xor_sync(0xffffffffu, rs0, 1);
        rs0 += __shfl_xor_sync(0xffffffffu, rs0, 2);
        rs1 += __shfl_xor_sync(0xffffffffu, rs1, 1);
        rs1 += __shfl_xor_sync(0xffffffffu, rs1, 2);
        l0 = l0*sc0 + rs0;
        l1 = l1*sc1 + rs1;
        #pragma unroll
        for (int nt = 0; nt < 8; nt++) {
            o[nt][0] *= sc0; o[nt][1] *= sc0;
            o[nt][2] *= sc1; o[nt][3] *= sc1;
        }

        // O += P * V   (k-dim = 64 keys; a-frags = pa registers)
        #pragma unroll
        for (int k0 = 0; k0 < 4; k0++) {
            const unsigned offB = ((unsigned)(32*k0 + 16*bsel)) ^ swb;
            #pragma unroll
            for (int p = 0; p < 4; p++) {
                unsigned b[4];
                LDSM4(b[0], b[1], b[2], b[3], vstg + kvB[p] + offB);
                mma_f16(o[2*p    ], pa[k0], b);
                mma_f16(o[2*p + 1], pa[k0], b + 2);
            }
        }
    }

    // epilogue: normalize, store fp16 AO for gemm<1>
    const float inv0 = 1.f / l0, inv1 = 1.f / l1;
    const int b = bh >> 4, h = bh & 15;
    const int r0 = q0 + wid*16 + lr, r1 = r0 + 8;
    unsigned* ao0 = (unsigned*)(g_AOh + ((size_t)(b*NT + r0))*NC + h*ND);
    unsigned* ao1 = (unsigned*)(g_AOh + ((size_t)(b*NT + r1))*NC + h*ND);
    #pragma unroll
    for (int nt = 0; nt < 8; nt++) {
        ao0[nt*4 + lc] = h2u(__floats2half2_rn(o[nt][0]*inv0, o[nt][1]*inv0));
        ao1[nt*4 + lc] = h2u(__floats2half2_rn(o[nt][2]*inv1, o[nt][3]*inv1));
    }
}

// ---------------------------------------------------------------------------
extern "C" void kernel_launch(void* const* d_in, const int* in_sizes, int n_in,
                              void* d_out, int out_size)
{
    const float* x     = (const float*)d_in[0];
    const float* Wqkv  = (const float*)d_in[1];
    const float* bqkv  = (const float*)d_in[2];
    const float* Wout  = (const float*)d_in[3];
    const float* bout  = (const float*)d_in[4];
    float* out = (float*)d_out;

    static int cfg_done = 0;
    if (!cfg_done) {
        cudaFuncSetAttribute(gemm_h<0>, cudaFuncAttributeMaxDynamicSharedMemorySize, GEMM_SMEM);
        cudaFuncSetAttribute(gemm_h<1>, cudaFuncAttributeMaxDynamicSharedMemorySize, GEMM_SMEM);
        cudaFuncSetAttribute(attn_mma,  cudaFuncAttributeMaxDynamicSharedMemorySize, ATTN_SMEM);
        cfg_done = 1;
    }

    void *xh, *wqh, *woh;
    cudaGetSymbolAddress(&xh,  g_xh);
    cudaGetSymbolAddress(&wqh, g_Wqh);
    cudaGetSymbolAddress(&woh, g_Woh);

    cvt_h<<<1184, 256>>>((const float4*)x,    (uint2*)xh,  NM*NC/4);
    cvt_h<<<1184, 256>>>((const float4*)Wqkv, (uint2*)wqh, N_QKV*NC/4);
    cvt_h<<<296,  256>>>((const float4*)Wout, (uint2*)woh, NC*NC/4);

    gemm_h<0><<<dim3(N_QKV/BN, NM/BM), 256, GEMM_SMEM>>>(bqkv, nullptr);
    attn_mma<<<dim3(NT/128, NB*NH), 256, ATTN_SMEM>>>();
    gemm_h<1><<<dim3(NC/BN, NM/BM), 256, GEMM_SMEM>>>(bout, out);
}